// round 13
// baseline (speedup 1.0000x reference)
#include <cuda_runtime.h>
#include <cuda_bf16.h>
#include <cstdint>

// Problem constants
#define S_DIM 8192
#define B_DIM 8192
#define ENC 256
#define C_DIM 25
#define K_RANK 25   // 0-based rank -> 26th smallest
#define CAP 4096    // per-row candidate capacity

// ------------------------------------------------------------------
// Scratch (device globals; allocation-free per harness rules)
// ------------------------------------------------------------------
__device__ __align__(256) uint2 g_cand[(size_t)S_DIM * CAP];            // 268 MB candidate heap
__device__ __align__(256) float g_sub[(size_t)S_DIM * 256];             // subset distances (8 MB)
__device__ __align__(256) float g_ehi[(size_t)B_DIM * ENC];             // tf32(e)
__device__ __align__(256) float g_qhi[(size_t)S_DIM * ENC];             // gathered tf32(q), unique
__device__ __align__(256) __nv_bfloat16 g_ecA[(size_t)B_DIM * 2 * ENC]; // [qh16 | ql16]
__device__ __align__(256) __nv_bfloat16 g_ecB[(size_t)B_DIM * 2 * ENC]; // [el16 | eh16]
__device__ __align__(256) __nv_bfloat16 g_qcA[(size_t)S_DIM * 2 * ENC]; // gathered corr-A, unique
__device__ float g_bound[S_DIM];
__device__ unsigned int g_ccount[S_DIM];
__device__ float g_e2[B_DIM];
__device__ float g_q2[S_DIM];
__device__ float g_maxg[B_DIM];
__device__ unsigned char g_grp[B_DIM];
// dedup machinery
__device__ int g_present[B_DIM];
__device__ int g_uslot[B_DIM];
__device__ int g_uidxs[S_DIM];
__device__ int g_nuniq;
__device__ float g_res[S_DIM];

// ------------------------------------------------------------------
// Base-ISA PTX helpers (harness compiles via compute_103: NO 'a' features)
// ------------------------------------------------------------------
__device__ __forceinline__ uint32_t smem_u32(const void* p) {
    uint32_t a;
    asm("{ .reg .u64 t; cvta.to.shared.u64 t, %1; cvt.u32.u64 %0, t; }"
        : "=r"(a) : "l"(p));
    return a;
}
__device__ __forceinline__ float tf32_rn(float x) {
    uint32_t u;
    asm("cvt.rna.tf32.f32 %0, %1;" : "=r"(u) : "f"(x));
    return __uint_as_float(u);
}
__device__ __forceinline__ void cp16(uint32_t dst, const void* src) {
    asm volatile("cp.async.cg.shared.global [%0], [%1], 16;" :: "r"(dst), "l"(src));
}
__device__ __forceinline__ void ldsm4(uint32_t* r, uint32_t addr) {
    asm volatile("ldmatrix.sync.aligned.m8n8.x4.shared.b16 {%0,%1,%2,%3}, [%4];"
                 : "=r"(r[0]), "=r"(r[1]), "=r"(r[2]), "=r"(r[3]) : "r"(addr));
}
__device__ __forceinline__ void mma_tf32(float* c, const uint32_t* a, const uint32_t* b) {
    asm volatile(
        "mma.sync.aligned.m16n8k8.row.col.f32.tf32.tf32.f32 "
        "{%0,%1,%2,%3}, {%4,%5,%6,%7}, {%8,%9}, {%0,%1,%2,%3};"
        : "+f"(c[0]), "+f"(c[1]), "+f"(c[2]), "+f"(c[3])
        : "r"(a[0]), "r"(a[1]), "r"(a[2]), "r"(a[3]), "r"(b[0]), "r"(b[1]));
}
__device__ __forceinline__ void mma_bf16(float* c, const uint32_t* a, const uint32_t* b) {
    asm volatile(
        "mma.sync.aligned.m16n8k16.row.col.f32.bf16.bf16.f32 "
        "{%0,%1,%2,%3}, {%4,%5,%6,%7}, {%8,%9}, {%0,%1,%2,%3};"
        : "+f"(c[0]), "+f"(c[1]), "+f"(c[2]), "+f"(c[3])
        : "r"(a[0]), "r"(a[1]), "r"(a[2]), "r"(a[3]), "r"(b[0]), "r"(b[1]));
}
#define SWZ(o) ((o) ^ (((o) >> 3) & 0x70))

// ------------------------------------------------------------------
// Kernel 0: init dedup state, counters, bounds
// ------------------------------------------------------------------
__global__ void init_kernel() {
    int i = blockIdx.x * blockDim.x + threadIdx.x;   // 8192 threads
    g_present[i] = 0;
    g_ccount[i]  = 0u;
    g_bound[i]   = -1.0f;       // no pushes for rows beyond nuniq
    if (i == 0) g_nuniq = 0;
}

// ------------------------------------------------------------------
// Kernel 1: e2, argmax/max, tf32 + bf16 splits.  One block per b-row.
// ------------------------------------------------------------------
__global__ void prep_kernel(const float* __restrict__ enc,
                            const float* __restrict__ cat) {
    int b = blockIdx.x;
    int t = threadIdx.x;

    float v  = enc[(size_t)b * ENC + t];
    float hi = tf32_rn(v);
    float lo = v - hi;
    g_ehi[(size_t)b * ENC + t] = hi;
    __nv_bfloat16 h16 = __float2bfloat16(hi);
    __nv_bfloat16 l16 = __float2bfloat16(lo);
    g_ecA[(size_t)b * 2 * ENC + t]       = h16;
    g_ecA[(size_t)b * 2 * ENC + ENC + t] = l16;
    g_ecB[(size_t)b * 2 * ENC + t]       = l16;
    g_ecB[(size_t)b * 2 * ENC + ENC + t] = h16;

    float sq = v * v;
    #pragma unroll
    for (int o = 16; o > 0; o >>= 1) sq += __shfl_xor_sync(0xFFFFFFFFu, sq, o);

    __shared__ float ws[8];
    if ((t & 31) == 0) ws[t >> 5] = sq;
    __syncthreads();
    if (t == 0) {
        float s = 0.f;
        #pragma unroll
        for (int i = 0; i < 8; i++) s += ws[i];
        g_e2[b] = s;
    }

    if (t < 32) {
        float mv = -1e30f;
        int   mi = 0x7FFFFFFF;
        if (t < C_DIM) { mv = cat[(size_t)b * C_DIM + t]; mi = t; }
        #pragma unroll
        for (int o = 16; o > 0; o >>= 1) {
            float ov = __shfl_xor_sync(0xFFFFFFFFu, mv, o);
            int   oi = __shfl_xor_sync(0xFFFFFFFFu, mi, o);
            if (ov > mv || (ov == mv && oi < mi)) { mv = ov; mi = oi; }
        }
        if (t == 0) { g_maxg[b] = mv; g_grp[b] = (unsigned char)mi; }
    }
}

// ------------------------------------------------------------------
// Kernel 1b: mark unique idx values, assign slots
// ------------------------------------------------------------------
__global__ void mark_kernel(const int* __restrict__ idxs) {
    int s = blockIdx.x * blockDim.x + threadIdx.x;
    if (s < S_DIM) {
        int idx = idxs[s];
        if (atomicCAS(&g_present[idx], 0, 1) == 0) {
            int slot = atomicAdd(&g_nuniq, 1);
            g_uslot[idx]  = slot;
            g_uidxs[slot] = idx;
        }
    }
}

// ------------------------------------------------------------------
// Kernel 2: gather unique q rows (tf32 + corrA) + q2
// ------------------------------------------------------------------
__global__ void gather_kernel() {
    int slot = blockIdx.x, t = threadIdx.x;   // 64 threads
    if (slot >= g_nuniq) return;
    int idx = g_uidxs[slot];
    const float4* sh = reinterpret_cast<const float4*>(&g_ehi[(size_t)idx * ENC]);
    float4* dh = reinterpret_cast<float4*>(&g_qhi[(size_t)slot * ENC]);
    dh[t] = sh[t];
    const uint4* sc = reinterpret_cast<const uint4*>(&g_ecA[(size_t)idx * 2 * ENC]);
    uint4* dc = reinterpret_cast<uint4*>(&g_qcA[(size_t)slot * 2 * ENC]);
    dc[t] = sc[t];
    if (t == 0) g_q2[slot] = g_e2[idx];
}

// ------------------------------------------------------------------
// Shared GEMM machinery (R9 config: 256 thr, warp grid 2x4, tile 64x64)
// ------------------------------------------------------------------
#define BM 128
#define BN 256
#define NCHUNK 8
#define AF32_OFF 0
#define ACOR_OFF (128 * 128)
#define BF32_OFF (2 * 128 * 128)
#define BCOR_OFF (BF32_OFF + 256 * 128)
#define STAGE    (BCOR_OFF + 256 * 128)         // 96 KB
#define GEMM_SMEM (2 * STAGE)                   // 192 KB

__device__ __forceinline__ void load_stage(uint32_t st, int brow, int bcol,
                                           int c, int tid) {
    const char* qcA = reinterpret_cast<const char*>(g_qcA);
    const char* ecB = reinterpret_cast<const char*>(g_ecB);
    #pragma unroll
    for (int it = 0; it < 4; ++it) {
        int i = tid + it * 256;
        int r = i >> 3, ch = i & 7;
        uint32_t off = SWZ((uint32_t)(r * 128 + ch * 16));
        cp16(st + AF32_OFF + off, g_qhi + (size_t)(brow + r) * ENC + c * 32 + ch * 4);
        cp16(st + ACOR_OFF + off, qcA + (size_t)(brow + r) * 1024 + c * 128 + ch * 16);
    }
    #pragma unroll
    for (int it = 0; it < 8; ++it) {
        int i = tid + it * 256;
        int r = i >> 3, ch = i & 7;
        uint32_t off = SWZ((uint32_t)(r * 128 + ch * 16));
        cp16(st + BF32_OFF + off, g_ehi + (size_t)(bcol + r) * ENC + c * 32 + ch * 4);
        cp16(st + BCOR_OFF + off, ecB + (size_t)(bcol + r) * 1024 + c * 128 + ch * 16);
    }
    asm volatile("cp.async.commit_group;" ::: "memory");
}

// Mainloop shared by both GEMM kernels (acc[4][8][4] accumulate)
__device__ __forceinline__ void gemm_mainloop(uint32_t dsm, int brow, int bcol,
                                              int tid, int lane, int warp_m,
                                              int warp_n, float acc[4][8][4]) {
    const int a_row = warp_m * 64 + (lane & 15);
    const int a_kb  = (lane >> 4) << 4;
    const int b_row = warp_n * 64 + ((lane >> 4) << 3) + (lane & 7);
    const int b_kb  = ((lane >> 3) & 1) << 4;

    load_stage(dsm,         brow, bcol, 0, tid);
    load_stage(dsm + STAGE, brow, bcol, 1, tid);

    #pragma unroll
    for (int c = 0; c < NCHUNK; ++c) {
        if (c == NCHUNK - 1) asm volatile("cp.async.wait_group 0;" ::: "memory");
        else                 asm volatile("cp.async.wait_group 1;" ::: "memory");
        __syncthreads();

        const uint32_t st = dsm + (c & 1) * STAGE;

        #pragma unroll
        for (int ks = 0; ks < 4; ++ks) {
            uint32_t ahi[4][4], aco[4][4], bhi[8][2], bco[8][2];
            #pragma unroll
            for (int im = 0; im < 4; ++im) {
                uint32_t off = SWZ((uint32_t)((a_row + im * 16) * 128 + ks * 32 + a_kb));
                ldsm4(ahi[im], st + AF32_OFF + off);
                ldsm4(aco[im], st + ACOR_OFF + off);
            }
            #pragma unroll
            for (int jn = 0; jn < 4; ++jn) {
                uint32_t off = SWZ((uint32_t)((b_row + jn * 16) * 128 + ks * 32 + b_kb));
                uint32_t rh[4], rc[4];
                ldsm4(rh, st + BF32_OFF + off);
                ldsm4(rc, st + BCOR_OFF + off);
                bhi[2 * jn][0] = rh[0]; bhi[2 * jn][1] = rh[1];
                bhi[2 * jn + 1][0] = rh[2]; bhi[2 * jn + 1][1] = rh[3];
                bco[2 * jn][0] = rc[0]; bco[2 * jn][1] = rc[1];
                bco[2 * jn + 1][0] = rc[2]; bco[2 * jn + 1][1] = rc[3];
            }
            #pragma unroll
            for (int im = 0; im < 4; ++im)
                #pragma unroll
                for (int j = 0; j < 8; ++j) {
                    mma_tf32(acc[im][j], ahi[im], bhi[j]);
                    mma_bf16(acc[im][j], aco[im], bco[j]);
                }
        }
        __syncthreads();
        if (c + 2 < NCHUNK)
            load_stage(dsm + (c & 1) * STAGE, brow, bcol, c + 2, tid);
    }
}

// ------------------------------------------------------------------
// Kernel 3a: bound GEMM — columns [0,256) only, writes g_sub.
// Bit-identical mainloop to the main GEMM -> values match exactly.
// ------------------------------------------------------------------
__global__ __launch_bounds__(256, 1)
void bound_gemm() {
    const int brow = blockIdx.y * BM;
    if (brow >= g_nuniq) return;

    extern __shared__ char dsm_raw[];
    __shared__ float e2s[BN];
    __shared__ float q2s[BM];

    const int tid    = threadIdx.x;
    const int lane   = tid & 31;
    const int wid    = tid >> 5;
    const int warp_m = wid & 1;
    const int warp_n = wid >> 1;
    const uint32_t dsm = smem_u32(dsm_raw);

    for (int i = tid; i < BN; i += 256) e2s[i] = g_e2[i];
    for (int i = tid; i < BM; i += 256) q2s[i] = g_q2[brow + i];

    float acc[4][8][4];
    #pragma unroll
    for (int im = 0; im < 4; im++)
        #pragma unroll
        for (int j = 0; j < 8; j++)
            #pragma unroll
            for (int v = 0; v < 4; v++) acc[im][j][v] = 0.f;

    gemm_mainloop(dsm, brow, 0, tid, lane, warp_m, warp_n, acc);

    #pragma unroll
    for (int im = 0; im < 4; ++im) {
        const int r0 = warp_m * 64 + im * 16 + (lane >> 2);
        const float q2a = q2s[r0];
        const float q2b = q2s[r0 + 8];
        #pragma unroll
        for (int j = 0; j < 8; ++j) {
            const int cl = warp_n * 64 + j * 8 + 2 * (lane & 3);
            const float e0 = e2s[cl], e1 = e2s[cl + 1];
            float2 oa, ob;
            oa.x = fmaxf(fmaf(-2.f, acc[im][j][0], q2a + e0), 0.f);
            oa.y = fmaxf(fmaf(-2.f, acc[im][j][1], q2a + e1), 0.f);
            ob.x = fmaxf(fmaf(-2.f, acc[im][j][2], q2b + e0), 0.f);
            ob.y = fmaxf(fmaf(-2.f, acc[im][j][3], q2b + e1), 0.f);
            *reinterpret_cast<float2*>(&g_sub[(size_t)(brow + r0) * 256 + cl]) = oa;
            *reinterpret_cast<float2*>(&g_sub[(size_t)(brow + r0 + 8) * 256 + cl]) = ob;
        }
    }
}

// ------------------------------------------------------------------
// Kernel 3b: per-row bound = exact 26th-smallest of subset + margin
// ------------------------------------------------------------------
__global__ __launch_bounds__(256)
void bound_select() {
    const int s = blockIdx.x;
    if (s >= g_nuniq) return;
    const int tid = threadIdx.x;
    __shared__ float sv[256];
    sv[tid] = g_sub[(size_t)s * 256 + tid];
    __syncthreads();
    float vi = sv[tid];
    int l = 0, e = 0;
    #pragma unroll 8
    for (int j = 0; j < 256; j++) {
        float vj = sv[j];
        l += (vj < vi);
        e += (vj == vi);
    }
    if (l <= K_RANK && K_RANK < l + e)
        g_bound[s] = vi + 0.25f;
}

// ------------------------------------------------------------------
// Kernel 3c: main GEMM — pushes candidates (val < bound), no d2 store.
// ------------------------------------------------------------------
__device__ __forceinline__ void push_cand(int row, float v, int col) {
    unsigned int p = atomicAdd(&g_ccount[row], 1u);
    if (p < CAP)
        g_cand[(size_t)row * CAP + p] = make_uint2(__float_as_uint(v), (unsigned)col);
}

__global__ __launch_bounds__(256, 1)
void dist_gemm_mma() {
    const int brow = blockIdx.y * BM;
    if (brow >= g_nuniq) return;

    extern __shared__ char dsm_raw[];
    __shared__ float e2s[BN];
    __shared__ float q2s[BM];
    __shared__ float bnds[BM];

    const int tid    = threadIdx.x;
    const int lane   = tid & 31;
    const int wid    = tid >> 5;
    const int warp_m = wid & 1;
    const int warp_n = wid >> 1;
    const int bcol   = blockIdx.x * BN;
    const uint32_t dsm = smem_u32(dsm_raw);

    for (int i = tid; i < BN; i += 256) e2s[i] = g_e2[bcol + i];
    for (int i = tid; i < BM; i += 256) {
        q2s[i]  = g_q2[brow + i];
        bnds[i] = g_bound[brow + i];
    }

    float acc[4][8][4];
    #pragma unroll
    for (int im = 0; im < 4; im++)
        #pragma unroll
        for (int j = 0; j < 8; j++)
            #pragma unroll
            for (int v = 0; v < 4; v++) acc[im][j][v] = 0.f;

    gemm_mainloop(dsm, brow, bcol, tid, lane, warp_m, warp_n, acc);

    #pragma unroll
    for (int im = 0; im < 4; ++im) {
        const int ra = brow + warp_m * 64 + im * 16 + (lane >> 2);
        const int rb = ra + 8;
        const float q2a = q2s[ra - brow];
        const float q2b = q2s[rb - brow];
        const float ba = bnds[ra - brow];
        const float bb = bnds[rb - brow];
        #pragma unroll
        for (int j = 0; j < 8; ++j) {
            const int cl = warp_n * 64 + j * 8 + 2 * (lane & 3);
            const int col = bcol + cl;
            const float e0 = e2s[cl], e1 = e2s[cl + 1];
            float v0 = fmaxf(fmaf(-2.f, acc[im][j][0], q2a + e0), 0.f);
            float v1 = fmaxf(fmaf(-2.f, acc[im][j][1], q2a + e1), 0.f);
            float v2 = fmaxf(fmaf(-2.f, acc[im][j][2], q2b + e0), 0.f);
            float v3 = fmaxf(fmaf(-2.f, acc[im][j][3], q2b + e1), 0.f);
            if (v0 < ba) push_cand(ra, v0, col);
            if (v1 < ba) push_cand(ra, v1, col + 1);
            if (v2 < bb) push_cand(rb, v2, col);
            if (v3 < bb) push_cand(rb, v3, col + 1);
        }
    }
}

// ------------------------------------------------------------------
// Kernel 4: select over candidate lists. Exact.
// ------------------------------------------------------------------
__global__ __launch_bounds__(256)
void select_kernel() {
    const int s = blockIdx.x;
    if (s >= g_nuniq) return;
    const int tid  = threadIdx.x;
    const int lane = tid & 31;
    const int wid  = tid >> 5;

    __shared__ uint32_t cand_v[CAP];     // 16 KB
    __shared__ uint32_t cand_c[CAP];     // 16 KB
    __shared__ uint32_t wred[8];
    __shared__ uint32_t sh_kbits;
    __shared__ int counts[C_DIM];

    const unsigned int mcnt = g_ccount[s];
    if (tid < C_DIM) counts[tid] = 0;

    if (mcnt <= CAP) {
        // ---- main path: candidates are complete ----
        const int m = (int)mcnt;
        for (int i = tid; i < m; i += 256) {
            uint2 c = g_cand[(size_t)s * CAP + i];
            cand_v[i] = c.x;
            cand_c[i] = c.y;
        }
        __syncthreads();

        // exact rank-25 among m (m >= 26 guaranteed by bound construction)
        for (int i = tid; i < m; i += 256) {
            uint32_t vi = cand_v[i];
            int l = 0, e = 0;
            for (int j = 0; j < m; j++) {
                uint32_t vj = cand_v[j];
                l += (vj < vi);
                e += (vj == vi);
            }
            if (l <= K_RANK && K_RANK < l + e) sh_kbits = vi;
        }
        __syncthreads();
        const uint32_t kbits = sh_kbits;

        for (int i = tid; i < m; i += 256) {
            if (cand_v[i] < kbits)
                atomicAdd(&counts[g_grp[cand_c[i]]], 1);
        }
        __syncthreads();
    } else {
        // ---- overflow fallback (essentially never): fp32 recompute +
        //      32-step binary search on value bits. Exact.
        __shared__ float qsh[ENC];
        for (int d = tid; d < ENC; d += 256)
            qsh[d] = g_qhi[(size_t)s * ENC + d] +
                     __bfloat162float(g_qcA[(size_t)s * 2 * ENC + ENC + d]);
        __syncthreads();
        const float q2v = g_q2[s];

        uint32_t v[32];
        for (int k = 0; k < 32; k++) {
            int col = tid + k * 256;
            float a = 0.f;
            for (int d = 0; d < ENC; d++) {
                float ev = g_ehi[(size_t)col * ENC + d] +
                           __bfloat162float(g_ecB[(size_t)col * 2 * ENC + d]);
                a = fmaf(qsh[d], ev, a);
            }
            v[k] = __float_as_uint(fmaxf(q2v + g_e2[col] - 2.f * a, 0.f));
        }

        auto count_lt = [&](uint32_t X) -> int {
            int c = 0;
            for (int k = 0; k < 32; k++) c += (int)(v[k] < X);
            #pragma unroll
            for (int o = 16; o > 0; o >>= 1)
                c += __shfl_xor_sync(0xFFFFFFFFu, c, o);
            if (lane == 0) wred[wid] = (uint32_t)c;
            __syncthreads();
            int t = 0;
            #pragma unroll
            for (int w = 0; w < 8; w++) t += (int)wred[w];
            __syncthreads();
            return t;
        };

        uint32_t lo = 0, hi = 0x7F800001u;
        while (hi - lo > 1) {
            uint32_t mid = lo + ((hi - lo) >> 1);
            if (count_lt(mid) >= K_RANK + 1) hi = mid;
            else                             lo = mid;
        }
        const uint32_t kbits = hi - 1;   // bits of the 26th-smallest value

        for (int k = 0; k < 32; k++) {
            if (v[k] < kbits)
                atomicAdd(&counts[g_grp[tid + k * 256]], 1);
        }
        __syncthreads();
    }

    if (tid == 0) {
        int n = 0;
        #pragma unroll
        for (int c = 0; c < C_DIM; c++) n += counts[c];
        float inv = 1.0f / (float)n;
        float purity = 0.f;
        #pragma unroll
        for (int c = 0; c < C_DIM; c++) {
            float p = (float)counts[c] * inv;
            purity -= p * logf(p + 1e-5f);
        }
        g_res[s] = purity * g_maxg[g_uidxs[s]];
    }
}

// ------------------------------------------------------------------
// Kernel 5: scatter per-slot results to all duplicate samples
// ------------------------------------------------------------------
__global__ void scatter_kernel(const int* __restrict__ idxs,
                               float* __restrict__ out) {
    int s = blockIdx.x * blockDim.x + threadIdx.x;
    if (s < S_DIM) out[s] = g_res[g_uslot[idxs[s]]];
}

// ------------------------------------------------------------------
// Launch
// ------------------------------------------------------------------
extern "C" void kernel_launch(void* const* d_in, const int* in_sizes, int n_in,
                              void* d_out, int out_size) {
    const float* enc  = (const float*)d_in[0];
    const float* cat  = (const float*)d_in[1];
    const int*   idxs = (const int*)d_in[2];
    float* out = (float*)d_out;

    static bool attr_done = false;
    if (!attr_done) {
        cudaFuncSetAttribute(dist_gemm_mma,
                             cudaFuncAttributeMaxDynamicSharedMemorySize, GEMM_SMEM);
        cudaFuncSetAttribute(bound_gemm,
                             cudaFuncAttributeMaxDynamicSharedMemorySize, GEMM_SMEM);
        attr_done = true;
    }

    init_kernel<<<32, 256>>>();
    prep_kernel<<<B_DIM, 256>>>(enc, cat);
    mark_kernel<<<S_DIM / 256, 256>>>(idxs);
    gather_kernel<<<S_DIM, 64>>>();

    dim3 bgrid(1, S_DIM / BM);
    bound_gemm<<<bgrid, 256, GEMM_SMEM>>>();
    bound_select<<<S_DIM, 256>>>();

    dim3 grid(B_DIM / BN, S_DIM / BM);
    dist_gemm_mma<<<grid, 256, GEMM_SMEM>>>();

    select_kernel<<<S_DIM, 256>>>();
    scatter_kernel<<<S_DIM / 256, 256>>>(idxs, out);
}

// round 14
// speedup vs baseline: 1.0881x; 1.0881x over previous
#include <cuda_runtime.h>
#include <cuda_bf16.h>
#include <cstdint>

// Problem constants
#define S_DIM 8192
#define B_DIM 8192
#define ENC 256
#define C_DIM 25
#define K_RANK 25   // 0-based rank -> 26th smallest
#define CAP 4096    // per-row candidate capacity

// ------------------------------------------------------------------
// Scratch (device globals; allocation-free per harness rules)
// ------------------------------------------------------------------
__device__ __align__(256) uint2 g_cand[(size_t)S_DIM * CAP];            // 268 MB candidate heap
__device__ __align__(256) float g_sub[(size_t)S_DIM * 256];             // subset distances (8 MB)
__device__ __align__(256) float g_ehi[(size_t)B_DIM * ENC];             // tf32(e)
__device__ __align__(256) float g_qhi[(size_t)S_DIM * ENC];             // gathered tf32(q), unique
__device__ __align__(256) __nv_bfloat16 g_ecA[(size_t)B_DIM * 2 * ENC]; // [qh16 | ql16]
__device__ __align__(256) __nv_bfloat16 g_ecB[(size_t)B_DIM * 2 * ENC]; // [el16 | eh16]
__device__ __align__(256) __nv_bfloat16 g_qcA[(size_t)S_DIM * 2 * ENC]; // gathered corr-A, unique
__device__ float g_bound[S_DIM];
__device__ unsigned int g_ccount[S_DIM];
__device__ float g_e2[B_DIM];
__device__ float g_q2[S_DIM];
__device__ float g_maxg[B_DIM];
__device__ unsigned char g_grp[B_DIM];
// dedup machinery
__device__ int g_present[B_DIM];
__device__ int g_uslot[B_DIM];
__device__ int g_uidxs[S_DIM];
__device__ int g_nuniq;
__device__ float g_res[S_DIM];

// ------------------------------------------------------------------
// Base-ISA PTX helpers (harness compiles via compute_103: NO 'a' features)
// ------------------------------------------------------------------
__device__ __forceinline__ uint32_t smem_u32(const void* p) {
    uint32_t a;
    asm("{ .reg .u64 t; cvta.to.shared.u64 t, %1; cvt.u32.u64 %0, t; }"
        : "=r"(a) : "l"(p));
    return a;
}
__device__ __forceinline__ float tf32_rn(float x) {
    uint32_t u;
    asm("cvt.rna.tf32.f32 %0, %1;" : "=r"(u) : "f"(x));
    return __uint_as_float(u);
}
__device__ __forceinline__ void cp16(uint32_t dst, const void* src) {
    asm volatile("cp.async.cg.shared.global [%0], [%1], 16;" :: "r"(dst), "l"(src));
}
__device__ __forceinline__ void ldsm4(uint32_t* r, uint32_t addr) {
    asm volatile("ldmatrix.sync.aligned.m8n8.x4.shared.b16 {%0,%1,%2,%3}, [%4];"
                 : "=r"(r[0]), "=r"(r[1]), "=r"(r[2]), "=r"(r[3]) : "r"(addr));
}
__device__ __forceinline__ void mma_tf32(float* c, const uint32_t* a, const uint32_t* b) {
    asm volatile(
        "mma.sync.aligned.m16n8k8.row.col.f32.tf32.tf32.f32 "
        "{%0,%1,%2,%3}, {%4,%5,%6,%7}, {%8,%9}, {%0,%1,%2,%3};"
        : "+f"(c[0]), "+f"(c[1]), "+f"(c[2]), "+f"(c[3])
        : "r"(a[0]), "r"(a[1]), "r"(a[2]), "r"(a[3]), "r"(b[0]), "r"(b[1]));
}
__device__ __forceinline__ void mma_bf16(float* c, const uint32_t* a, const uint32_t* b) {
    asm volatile(
        "mma.sync.aligned.m16n8k16.row.col.f32.bf16.bf16.f32 "
        "{%0,%1,%2,%3}, {%4,%5,%6,%7}, {%8,%9}, {%0,%1,%2,%3};"
        : "+f"(c[0]), "+f"(c[1]), "+f"(c[2]), "+f"(c[3])
        : "r"(a[0]), "r"(a[1]), "r"(a[2]), "r"(a[3]), "r"(b[0]), "r"(b[1]));
}
#define SWZ(o) ((o) ^ (((o) >> 3) & 0x70))

// ------------------------------------------------------------------
// Kernel 0: init dedup state, counters, bounds
// ------------------------------------------------------------------
__global__ void init_kernel() {
    int i = blockIdx.x * blockDim.x + threadIdx.x;   // 8192 threads
    g_present[i] = 0;
    g_ccount[i]  = 0u;
    g_bound[i]   = -1.0f;       // no pushes for rows beyond nuniq
    if (i == 0) g_nuniq = 0;
}

// ------------------------------------------------------------------
// Kernel 1: e2, argmax/max, tf32 + bf16 splits.  One block per b-row.
// ------------------------------------------------------------------
__global__ void prep_kernel(const float* __restrict__ enc,
                            const float* __restrict__ cat) {
    int b = blockIdx.x;
    int t = threadIdx.x;

    float v  = enc[(size_t)b * ENC + t];
    float hi = tf32_rn(v);
    float lo = v - hi;
    g_ehi[(size_t)b * ENC + t] = hi;
    __nv_bfloat16 h16 = __float2bfloat16(hi);
    __nv_bfloat16 l16 = __float2bfloat16(lo);
    g_ecA[(size_t)b * 2 * ENC + t]       = h16;
    g_ecA[(size_t)b * 2 * ENC + ENC + t] = l16;
    g_ecB[(size_t)b * 2 * ENC + t]       = l16;
    g_ecB[(size_t)b * 2 * ENC + ENC + t] = h16;

    float sq = v * v;
    #pragma unroll
    for (int o = 16; o > 0; o >>= 1) sq += __shfl_xor_sync(0xFFFFFFFFu, sq, o);

    __shared__ float ws[8];
    if ((t & 31) == 0) ws[t >> 5] = sq;
    __syncthreads();
    if (t == 0) {
        float s = 0.f;
        #pragma unroll
        for (int i = 0; i < 8; i++) s += ws[i];
        g_e2[b] = s;
    }

    if (t < 32) {
        float mv = -1e30f;
        int   mi = 0x7FFFFFFF;
        if (t < C_DIM) { mv = cat[(size_t)b * C_DIM + t]; mi = t; }
        #pragma unroll
        for (int o = 16; o > 0; o >>= 1) {
            float ov = __shfl_xor_sync(0xFFFFFFFFu, mv, o);
            int   oi = __shfl_xor_sync(0xFFFFFFFFu, mi, o);
            if (ov > mv || (ov == mv && oi < mi)) { mv = ov; mi = oi; }
        }
        if (t == 0) { g_maxg[b] = mv; g_grp[b] = (unsigned char)mi; }
    }
}

// ------------------------------------------------------------------
// Kernel 1b: mark unique idx values, assign slots
// ------------------------------------------------------------------
__global__ void mark_kernel(const int* __restrict__ idxs) {
    int s = blockIdx.x * blockDim.x + threadIdx.x;
    if (s < S_DIM) {
        int idx = idxs[s];
        if (atomicCAS(&g_present[idx], 0, 1) == 0) {
            int slot = atomicAdd(&g_nuniq, 1);
            g_uslot[idx]  = slot;
            g_uidxs[slot] = idx;
        }
    }
}

// ------------------------------------------------------------------
// Kernel 2: gather unique q rows (tf32 + corrA) + q2
// ------------------------------------------------------------------
__global__ void gather_kernel() {
    int slot = blockIdx.x, t = threadIdx.x;   // 64 threads
    if (slot >= g_nuniq) return;
    int idx = g_uidxs[slot];
    const float4* sh = reinterpret_cast<const float4*>(&g_ehi[(size_t)idx * ENC]);
    float4* dh = reinterpret_cast<float4*>(&g_qhi[(size_t)slot * ENC]);
    dh[t] = sh[t];
    const uint4* sc = reinterpret_cast<const uint4*>(&g_ecA[(size_t)idx * 2 * ENC]);
    uint4* dc = reinterpret_cast<uint4*>(&g_qcA[(size_t)slot * 2 * ENC]);
    dc[t] = sc[t];
    if (t == 0) g_q2[slot] = g_e2[idx];
}

// ------------------------------------------------------------------
// Shared GEMM constants (R10 config: 512 threads, warp grid 4x4)
// ------------------------------------------------------------------
#define BM 128
#define BN 256
#define NCHUNK 8
#define NTHREADS 512
#define AF32_OFF 0
#define ACOR_OFF (128 * 128)
#define BF32_OFF (2 * 128 * 128)
#define BCOR_OFF (BF32_OFF + 256 * 128)
#define STAGE    (BCOR_OFF + 256 * 128)         // 96 KB
#define GEMM_SMEM (2 * STAGE)                   // 192 KB

__device__ __forceinline__ void load_stage(uint32_t st, int brow, int bcol,
                                           int c, int tid) {
    const char* qcA = reinterpret_cast<const char*>(g_qcA);
    const char* ecB = reinterpret_cast<const char*>(g_ecB);
    #pragma unroll
    for (int it = 0; it < 2; ++it) {
        int i = tid + it * NTHREADS;
        int r = i >> 3, ch = i & 7;
        uint32_t off = SWZ((uint32_t)(r * 128 + ch * 16));
        cp16(st + AF32_OFF + off, g_qhi + (size_t)(brow + r) * ENC + c * 32 + ch * 4);
        cp16(st + ACOR_OFF + off, qcA + (size_t)(brow + r) * 1024 + c * 128 + ch * 16);
    }
    #pragma unroll
    for (int it = 0; it < 4; ++it) {
        int i = tid + it * NTHREADS;
        int r = i >> 3, ch = i & 7;
        uint32_t off = SWZ((uint32_t)(r * 128 + ch * 16));
        cp16(st + BF32_OFF + off, g_ehi + (size_t)(bcol + r) * ENC + c * 32 + ch * 4);
        cp16(st + BCOR_OFF + off, ecB + (size_t)(bcol + r) * 1024 + c * 128 + ch * 16);
    }
    asm volatile("cp.async.commit_group;" ::: "memory");
}

// Mainloop body, textually duplicated in both kernels via macro to keep
// acc in registers (NO array-through-function: that spilled in R13).
#define GEMM_MAINLOOP(dsm, brow, bcol)                                          \
    load_stage(dsm,         brow, bcol, 0, tid);                                \
    load_stage(dsm + STAGE, brow, bcol, 1, tid);                                \
    _Pragma("unroll")                                                           \
    for (int c = 0; c < NCHUNK; ++c) {                                          \
        if (c == NCHUNK - 1) asm volatile("cp.async.wait_group 0;" ::: "memory");\
        else                 asm volatile("cp.async.wait_group 1;" ::: "memory");\
        __syncthreads();                                                        \
        const uint32_t st = dsm + (c & 1) * STAGE;                              \
        _Pragma("unroll")                                                       \
        for (int ks = 0; ks < 4; ++ks) {                                        \
            uint32_t ahi[2][4], aco[2][4], bhi[8][2], bco[8][2];                \
            _Pragma("unroll")                                                   \
            for (int im = 0; im < 2; ++im) {                                    \
                uint32_t off = SWZ((uint32_t)((a_row + im * 16) * 128 + ks * 32 + a_kb)); \
                ldsm4(ahi[im], st + AF32_OFF + off);                            \
                ldsm4(aco[im], st + ACOR_OFF + off);                            \
            }                                                                   \
            _Pragma("unroll")                                                   \
            for (int jn = 0; jn < 4; ++jn) {                                    \
                uint32_t off = SWZ((uint32_t)((b_row + jn * 16) * 128 + ks * 32 + b_kb)); \
                uint32_t rh[4], rc[4];                                          \
                ldsm4(rh, st + BF32_OFF + off);                                 \
                ldsm4(rc, st + BCOR_OFF + off);                                 \
                bhi[2 * jn][0] = rh[0]; bhi[2 * jn][1] = rh[1];                 \
                bhi[2 * jn + 1][0] = rh[2]; bhi[2 * jn + 1][1] = rh[3];         \
                bco[2 * jn][0] = rc[0]; bco[2 * jn][1] = rc[1];                 \
                bco[2 * jn + 1][0] = rc[2]; bco[2 * jn + 1][1] = rc[3];         \
            }                                                                   \
            _Pragma("unroll")                                                   \
            for (int im = 0; im < 2; ++im)                                      \
                _Pragma("unroll")                                               \
                for (int j = 0; j < 8; ++j) {                                   \
                    mma_tf32(acc[im][j], ahi[im], bhi[j]);                      \
                    mma_bf16(acc[im][j], aco[im], bco[j]);                      \
                }                                                               \
        }                                                                       \
        __syncthreads();                                                        \
        if (c + 2 < NCHUNK)                                                     \
            load_stage(dsm + (c & 1) * STAGE, brow, bcol, c + 2, tid);          \
    }

// ------------------------------------------------------------------
// Kernel 3a: bound GEMM — columns [0,256) only, writes g_sub.
// Bit-identical mainloop to the main GEMM -> values match exactly.
// ------------------------------------------------------------------
__global__ __launch_bounds__(NTHREADS, 1)
void bound_gemm() {
    const int brow = blockIdx.y * BM;
    if (brow >= g_nuniq) return;

    extern __shared__ char dsm_raw[];
    __shared__ float e2s[BN];
    __shared__ float q2s[BM];

    const int tid    = threadIdx.x;
    const int lane   = tid & 31;
    const int wid    = tid >> 5;
    const int warp_m = wid & 3;
    const int warp_n = wid >> 2;
    const uint32_t dsm = smem_u32(dsm_raw);

    for (int i = tid; i < BN; i += NTHREADS) e2s[i] = g_e2[i];
    for (int i = tid; i < BM; i += NTHREADS) q2s[i] = g_q2[brow + i];

    float acc[2][8][4];
    #pragma unroll
    for (int im = 0; im < 2; im++)
        #pragma unroll
        for (int j = 0; j < 8; j++)
            #pragma unroll
            for (int v = 0; v < 4; v++) acc[im][j][v] = 0.f;

    const int a_row = warp_m * 32 + (lane & 15);
    const int a_kb  = (lane >> 4) << 4;
    const int b_row = warp_n * 64 + ((lane >> 4) << 3) + (lane & 7);
    const int b_kb  = ((lane >> 3) & 1) << 4;

    GEMM_MAINLOOP(dsm, brow, 0)

    #pragma unroll
    for (int im = 0; im < 2; ++im) {
        const int r0 = warp_m * 32 + im * 16 + (lane >> 2);
        const float q2a = q2s[r0];
        const float q2b = q2s[r0 + 8];
        #pragma unroll
        for (int j = 0; j < 8; ++j) {
            const int cl = warp_n * 64 + j * 8 + 2 * (lane & 3);
            const float e0 = e2s[cl], e1 = e2s[cl + 1];
            float2 oa, ob;
            oa.x = fmaxf(fmaf(-2.f, acc[im][j][0], q2a + e0), 0.f);
            oa.y = fmaxf(fmaf(-2.f, acc[im][j][1], q2a + e1), 0.f);
            ob.x = fmaxf(fmaf(-2.f, acc[im][j][2], q2b + e0), 0.f);
            ob.y = fmaxf(fmaf(-2.f, acc[im][j][3], q2b + e1), 0.f);
            *reinterpret_cast<float2*>(&g_sub[(size_t)(brow + r0) * 256 + cl]) = oa;
            *reinterpret_cast<float2*>(&g_sub[(size_t)(brow + r0 + 8) * 256 + cl]) = ob;
        }
    }
}

// ------------------------------------------------------------------
// Kernel 3b: per-row bound = exact 26th-smallest of subset + margin
// ------------------------------------------------------------------
__global__ __launch_bounds__(256)
void bound_select() {
    const int s = blockIdx.x;
    if (s >= g_nuniq) return;
    const int tid = threadIdx.x;
    __shared__ float sv[256];
    sv[tid] = g_sub[(size_t)s * 256 + tid];
    __syncthreads();
    float vi = sv[tid];
    int l = 0, e = 0;
    #pragma unroll 8
    for (int j = 0; j < 256; j++) {
        float vj = sv[j];
        l += (vj < vi);
        e += (vj == vi);
    }
    if (l <= K_RANK && K_RANK < l + e)
        g_bound[s] = vi + 0.25f;
}

// ------------------------------------------------------------------
// Kernel 3c: main GEMM — pushes candidates (val < bound), no d2 store.
// ------------------------------------------------------------------
__device__ __forceinline__ void push_cand(int row, float v, int col) {
    unsigned int p = atomicAdd(&g_ccount[row], 1u);
    if (p < CAP)
        g_cand[(size_t)row * CAP + p] = make_uint2(__float_as_uint(v), (unsigned)col);
}

__global__ __launch_bounds__(NTHREADS, 1)
void dist_gemm_mma() {
    const int brow = blockIdx.y * BM;
    if (brow >= g_nuniq) return;

    extern __shared__ char dsm_raw[];
    __shared__ float e2s[BN];
    __shared__ float q2s[BM];
    __shared__ float bnds[BM];

    const int tid    = threadIdx.x;
    const int lane   = tid & 31;
    const int wid    = tid >> 5;
    const int warp_m = wid & 3;
    const int warp_n = wid >> 2;
    const int bcol   = blockIdx.x * BN;
    const uint32_t dsm = smem_u32(dsm_raw);

    for (int i = tid; i < BN; i += NTHREADS) e2s[i] = g_e2[bcol + i];
    for (int i = tid; i < BM; i += NTHREADS) {
        q2s[i]  = g_q2[brow + i];
        bnds[i] = g_bound[brow + i];
    }

    float acc[2][8][4];
    #pragma unroll
    for (int im = 0; im < 2; im++)
        #pragma unroll
        for (int j = 0; j < 8; j++)
            #pragma unroll
            for (int v = 0; v < 4; v++) acc[im][j][v] = 0.f;

    const int a_row = warp_m * 32 + (lane & 15);
    const int a_kb  = (lane >> 4) << 4;
    const int b_row = warp_n * 64 + ((lane >> 4) << 3) + (lane & 7);
    const int b_kb  = ((lane >> 3) & 1) << 4;

    GEMM_MAINLOOP(dsm, brow, bcol)

    #pragma unroll
    for (int im = 0; im < 2; ++im) {
        const int rl = warp_m * 32 + im * 16 + (lane >> 2);
        const int ra = brow + rl;
        const float q2a = q2s[rl];
        const float q2b = q2s[rl + 8];
        const float ba = bnds[rl];
        const float bb = bnds[rl + 8];
        #pragma unroll
        for (int j = 0; j < 8; ++j) {
            const int cl = warp_n * 64 + j * 8 + 2 * (lane & 3);
            const int col = bcol + cl;
            const float e0 = e2s[cl], e1 = e2s[cl + 1];
            float v0 = fmaxf(fmaf(-2.f, acc[im][j][0], q2a + e0), 0.f);
            float v1 = fmaxf(fmaf(-2.f, acc[im][j][1], q2a + e1), 0.f);
            float v2 = fmaxf(fmaf(-2.f, acc[im][j][2], q2b + e0), 0.f);
            float v3 = fmaxf(fmaf(-2.f, acc[im][j][3], q2b + e1), 0.f);
            if (v0 < ba) push_cand(ra, v0, col);
            if (v1 < ba) push_cand(ra, v1, col + 1);
            if (v2 < bb) push_cand(ra + 8, v2, col);
            if (v3 < bb) push_cand(ra + 8, v3, col + 1);
        }
    }
}

// ------------------------------------------------------------------
// Kernel 4: select over candidate lists. Exact.
// ------------------------------------------------------------------
__global__ __launch_bounds__(256)
void select_kernel() {
    const int s = blockIdx.x;
    if (s >= g_nuniq) return;
    const int tid  = threadIdx.x;
    const int lane = tid & 31;
    const int wid  = tid >> 5;

    __shared__ uint32_t cand_v[CAP];     // 16 KB
    __shared__ uint32_t cand_c[CAP];     // 16 KB
    __shared__ uint32_t wred[8];
    __shared__ uint32_t sh_kbits;
    __shared__ int counts[C_DIM];

    const unsigned int mcnt = g_ccount[s];
    if (tid < C_DIM) counts[tid] = 0;

    if (mcnt <= CAP) {
        const int m = (int)mcnt;
        for (int i = tid; i < m; i += 256) {
            uint2 c = g_cand[(size_t)s * CAP + i];
            cand_v[i] = c.x;
            cand_c[i] = c.y;
        }
        __syncthreads();

        for (int i = tid; i < m; i += 256) {
            uint32_t vi = cand_v[i];
            int l = 0, e = 0;
            for (int j = 0; j < m; j++) {
                uint32_t vj = cand_v[j];
                l += (vj < vi);
                e += (vj == vi);
            }
            if (l <= K_RANK && K_RANK < l + e) sh_kbits = vi;
        }
        __syncthreads();
        const uint32_t kbits = sh_kbits;

        for (int i = tid; i < m; i += 256) {
            if (cand_v[i] < kbits)
                atomicAdd(&counts[g_grp[cand_c[i]]], 1);
        }
        __syncthreads();
    } else {
        // ---- overflow fallback (essentially never): fp32 recompute +
        //      binary search on value bits. Exact.
        __shared__ float qsh[ENC];
        for (int d = tid; d < ENC; d += 256)
            qsh[d] = g_qhi[(size_t)s * ENC + d] +
                     __bfloat162float(g_qcA[(size_t)s * 2 * ENC + ENC + d]);
        __syncthreads();
        const float q2v = g_q2[s];

        uint32_t v[32];
        for (int k = 0; k < 32; k++) {
            int col = tid + k * 256;
            float a = 0.f;
            for (int d = 0; d < ENC; d++) {
                float ev = g_ehi[(size_t)col * ENC + d] +
                           __bfloat162float(g_ecB[(size_t)col * 2 * ENC + d]);
                a = fmaf(qsh[d], ev, a);
            }
            v[k] = __float_as_uint(fmaxf(q2v + g_e2[col] - 2.f * a, 0.f));
        }

        auto count_lt = [&](uint32_t X) -> int {
            int c = 0;
            for (int k = 0; k < 32; k++) c += (int)(v[k] < X);
            #pragma unroll
            for (int o = 16; o > 0; o >>= 1)
                c += __shfl_xor_sync(0xFFFFFFFFu, c, o);
            if (lane == 0) wred[wid] = (uint32_t)c;
            __syncthreads();
            int t = 0;
            #pragma unroll
            for (int w = 0; w < 8; w++) t += (int)wred[w];
            __syncthreads();
            return t;
        };

        uint32_t lo = 0, hi = 0x7F800001u;
        while (hi - lo > 1) {
            uint32_t mid = lo + ((hi - lo) >> 1);
            if (count_lt(mid) >= K_RANK + 1) hi = mid;
            else                             lo = mid;
        }
        const uint32_t kbits = hi - 1;

        for (int k = 0; k < 32; k++) {
            if (v[k] < kbits)
                atomicAdd(&counts[g_grp[tid + k * 256]], 1);
        }
        __syncthreads();
    }

    if (tid == 0) {
        int n = 0;
        #pragma unroll
        for (int c = 0; c < C_DIM; c++) n += counts[c];
        float inv = 1.0f / (float)n;
        float purity = 0.f;
        #pragma unroll
        for (int c = 0; c < C_DIM; c++) {
            float p = (float)counts[c] * inv;
            purity -= p * logf(p + 1e-5f);
        }
        g_res[s] = purity * g_maxg[g_uidxs[s]];
    }
}

// ------------------------------------------------------------------
// Kernel 5: scatter per-slot results to all duplicate samples
// ------------------------------------------------------------------
__global__ void scatter_kernel(const int* __restrict__ idxs,
                               float* __restrict__ out) {
    int s = blockIdx.x * blockDim.x + threadIdx.x;
    if (s < S_DIM) out[s] = g_res[g_uslot[idxs[s]]];
}

// ------------------------------------------------------------------
// Launch
// ------------------------------------------------------------------
extern "C" void kernel_launch(void* const* d_in, const int* in_sizes, int n_in,
                              void* d_out, int out_size) {
    const float* enc  = (const float*)d_in[0];
    const float* cat  = (const float*)d_in[1];
    const int*   idxs = (const int*)d_in[2];
    float* out = (float*)d_out;

    static bool attr_done = false;
    if (!attr_done) {
        cudaFuncSetAttribute(dist_gemm_mma,
                             cudaFuncAttributeMaxDynamicSharedMemorySize, GEMM_SMEM);
        cudaFuncSetAttribute(bound_gemm,
                             cudaFuncAttributeMaxDynamicSharedMemorySize, GEMM_SMEM);
        attr_done = true;
    }

    init_kernel<<<32, 256>>>();
    prep_kernel<<<B_DIM, 256>>>(enc, cat);
    mark_kernel<<<S_DIM / 256, 256>>>(idxs);
    gather_kernel<<<S_DIM, 64>>>();

    dim3 bgrid(1, S_DIM / BM);
    bound_gemm<<<bgrid, NTHREADS, GEMM_SMEM>>>();
    bound_select<<<S_DIM, 256>>>();

    dim3 grid(B_DIM / BN, S_DIM / BM);
    dist_gemm_mma<<<grid, NTHREADS, GEMM_SMEM>>>();

    select_kernel<<<S_DIM, 256>>>();
    scatter_kernel<<<S_DIM / 256, 256>>>(idxs, out);
}

// round 15
// speedup vs baseline: 2.2649x; 2.0815x over previous
#include <cuda_runtime.h>
#include <cuda_bf16.h>
#include <cstdint>

// Problem constants
#define S_DIM 8192
#define B_DIM 8192
#define ENC 256
#define C_DIM 25
#define K_RANK 25   // 0-based rank -> 26th smallest
#define CAP 4096    // per-row candidate capacity

// ------------------------------------------------------------------
// Scratch (device globals; allocation-free per harness rules)
// ------------------------------------------------------------------
__device__ __align__(256) uint2 g_cand[(size_t)S_DIM * CAP];            // 268 MB candidate heap
__device__ __align__(256) float g_sub[(size_t)S_DIM * 256];             // subset distances (8 MB)
__device__ __align__(256) float g_ehi[(size_t)B_DIM * ENC];             // tf32(e)
__device__ __align__(256) float g_qhi[(size_t)S_DIM * ENC];             // gathered tf32(q), unique
__device__ __align__(256) __nv_bfloat16 g_ecA[(size_t)B_DIM * 2 * ENC]; // [qh16 | ql16]
__device__ __align__(256) __nv_bfloat16 g_ecB[(size_t)B_DIM * 2 * ENC]; // [el16 | eh16]
__device__ __align__(256) __nv_bfloat16 g_qcA[(size_t)S_DIM * 2 * ENC]; // gathered corr-A, unique
__device__ float g_bound[S_DIM];
__device__ unsigned int g_ccount[S_DIM];
__device__ float g_e2[B_DIM];
__device__ float g_q2[S_DIM];
__device__ float g_maxg[B_DIM];
__device__ unsigned char g_grp[B_DIM];
// dedup machinery
__device__ int g_present[B_DIM];
__device__ int g_uslot[B_DIM];
__device__ int g_uidxs[S_DIM];
__device__ int g_nuniq;
__device__ float g_res[S_DIM];

// ------------------------------------------------------------------
// Base-ISA PTX helpers (harness compiles via compute_103: NO 'a' features)
// ------------------------------------------------------------------
__device__ __forceinline__ uint32_t smem_u32(const void* p) {
    uint32_t a;
    asm("{ .reg .u64 t; cvta.to.shared.u64 t, %1; cvt.u32.u64 %0, t; }"
        : "=r"(a) : "l"(p));
    return a;
}
__device__ __forceinline__ float tf32_rn(float x) {
    uint32_t u;
    asm("cvt.rna.tf32.f32 %0, %1;" : "=r"(u) : "f"(x));
    return __uint_as_float(u);
}
__device__ __forceinline__ void cp16(uint32_t dst, const void* src) {
    asm volatile("cp.async.cg.shared.global [%0], [%1], 16;" :: "r"(dst), "l"(src));
}
__device__ __forceinline__ void ldsm4(uint32_t* r, uint32_t addr) {
    asm volatile("ldmatrix.sync.aligned.m8n8.x4.shared.b16 {%0,%1,%2,%3}, [%4];"
                 : "=r"(r[0]), "=r"(r[1]), "=r"(r[2]), "=r"(r[3]) : "r"(addr));
}
__device__ __forceinline__ void mma_tf32(float* c, const uint32_t* a, const uint32_t* b) {
    asm volatile(
        "mma.sync.aligned.m16n8k8.row.col.f32.tf32.tf32.f32 "
        "{%0,%1,%2,%3}, {%4,%5,%6,%7}, {%8,%9}, {%0,%1,%2,%3};"
        : "+f"(c[0]), "+f"(c[1]), "+f"(c[2]), "+f"(c[3])
        : "r"(a[0]), "r"(a[1]), "r"(a[2]), "r"(a[3]), "r"(b[0]), "r"(b[1]));
}
__device__ __forceinline__ void mma_bf16(float* c, const uint32_t* a, const uint32_t* b) {
    asm volatile(
        "mma.sync.aligned.m16n8k16.row.col.f32.bf16.bf16.f32 "
        "{%0,%1,%2,%3}, {%4,%5,%6,%7}, {%8,%9}, {%0,%1,%2,%3};"
        : "+f"(c[0]), "+f"(c[1]), "+f"(c[2]), "+f"(c[3])
        : "r"(a[0]), "r"(a[1]), "r"(a[2]), "r"(a[3]), "r"(b[0]), "r"(b[1]));
}
#define SWZ(o) ((o) ^ (((o) >> 3) & 0x70))

// ------------------------------------------------------------------
// Kernel 0: init dedup state, counters, bounds
// ------------------------------------------------------------------
__global__ void init_kernel() {
    int i = blockIdx.x * blockDim.x + threadIdx.x;   // 8192 threads
    g_present[i] = 0;
    g_ccount[i]  = 0u;
    g_bound[i]   = -1.0f;       // no pushes for rows beyond nuniq
    if (i == 0) g_nuniq = 0;
}

// ------------------------------------------------------------------
// Kernel 1: e2, argmax/max, tf32 + bf16 splits.  One block per b-row.
// ------------------------------------------------------------------
__global__ void prep_kernel(const float* __restrict__ enc,
                            const float* __restrict__ cat) {
    int b = blockIdx.x;
    int t = threadIdx.x;

    float v  = enc[(size_t)b * ENC + t];
    float hi = tf32_rn(v);
    float lo = v - hi;
    g_ehi[(size_t)b * ENC + t] = hi;
    __nv_bfloat16 h16 = __float2bfloat16(hi);
    __nv_bfloat16 l16 = __float2bfloat16(lo);
    g_ecA[(size_t)b * 2 * ENC + t]       = h16;
    g_ecA[(size_t)b * 2 * ENC + ENC + t] = l16;
    g_ecB[(size_t)b * 2 * ENC + t]       = l16;
    g_ecB[(size_t)b * 2 * ENC + ENC + t] = h16;

    float sq = v * v;
    #pragma unroll
    for (int o = 16; o > 0; o >>= 1) sq += __shfl_xor_sync(0xFFFFFFFFu, sq, o);

    __shared__ float ws[8];
    if ((t & 31) == 0) ws[t >> 5] = sq;
    __syncthreads();
    if (t == 0) {
        float s = 0.f;
        #pragma unroll
        for (int i = 0; i < 8; i++) s += ws[i];
        g_e2[b] = s;
    }

    if (t < 32) {
        float mv = -1e30f;
        int   mi = 0x7FFFFFFF;
        if (t < C_DIM) { mv = cat[(size_t)b * C_DIM + t]; mi = t; }
        #pragma unroll
        for (int o = 16; o > 0; o >>= 1) {
            float ov = __shfl_xor_sync(0xFFFFFFFFu, mv, o);
            int   oi = __shfl_xor_sync(0xFFFFFFFFu, mi, o);
            if (ov > mv || (ov == mv && oi < mi)) { mv = ov; mi = oi; }
        }
        if (t == 0) { g_maxg[b] = mv; g_grp[b] = (unsigned char)mi; }
    }
}

// ------------------------------------------------------------------
// Kernel 1b: mark unique idx values, assign slots
// ------------------------------------------------------------------
__global__ void mark_kernel(const int* __restrict__ idxs) {
    int s = blockIdx.x * blockDim.x + threadIdx.x;
    if (s < S_DIM) {
        int idx = idxs[s];
        if (atomicCAS(&g_present[idx], 0, 1) == 0) {
            int slot = atomicAdd(&g_nuniq, 1);
            g_uslot[idx]  = slot;
            g_uidxs[slot] = idx;
        }
    }
}

// ------------------------------------------------------------------
// Kernel 2: gather unique q rows (tf32 + corrA) + q2
// ------------------------------------------------------------------
__global__ void gather_kernel() {
    int slot = blockIdx.x, t = threadIdx.x;   // 64 threads
    if (slot >= g_nuniq) return;
    int idx = g_uidxs[slot];
    const float4* sh = reinterpret_cast<const float4*>(&g_ehi[(size_t)idx * ENC]);
    float4* dh = reinterpret_cast<float4*>(&g_qhi[(size_t)slot * ENC]);
    dh[t] = sh[t];
    const uint4* sc = reinterpret_cast<const uint4*>(&g_ecA[(size_t)idx * 2 * ENC]);
    uint4* dc = reinterpret_cast<uint4*>(&g_qcA[(size_t)slot * 2 * ENC]);
    dc[t] = sc[t];
    if (t == 0) g_q2[slot] = g_e2[idx];
}

// ------------------------------------------------------------------
// Shared GEMM constants (R10 config: 512 threads, warp grid 4x4)
// ------------------------------------------------------------------
#define BM 128
#define BN 256
#define NCHUNK 8
#define NTHREADS 512
#define AF32_OFF 0
#define ACOR_OFF (128 * 128)
#define BF32_OFF (2 * 128 * 128)
#define BCOR_OFF (BF32_OFF + 256 * 128)
#define STAGE    (BCOR_OFF + 256 * 128)         // 96 KB
#define GEMM_SMEM (2 * STAGE)                   // 192 KB

__device__ __forceinline__ void load_stage(uint32_t st, int brow, int bcol,
                                           int c, int tid) {
    const char* qcA = reinterpret_cast<const char*>(g_qcA);
    const char* ecB = reinterpret_cast<const char*>(g_ecB);
    #pragma unroll
    for (int it = 0; it < 2; ++it) {
        int i = tid + it * NTHREADS;
        int r = i >> 3, ch = i & 7;
        uint32_t off = SWZ((uint32_t)(r * 128 + ch * 16));
        cp16(st + AF32_OFF + off, g_qhi + (size_t)(brow + r) * ENC + c * 32 + ch * 4);
        cp16(st + ACOR_OFF + off, qcA + (size_t)(brow + r) * 1024 + c * 128 + ch * 16);
    }
    #pragma unroll
    for (int it = 0; it < 4; ++it) {
        int i = tid + it * NTHREADS;
        int r = i >> 3, ch = i & 7;
        uint32_t off = SWZ((uint32_t)(r * 128 + ch * 16));
        cp16(st + BF32_OFF + off, g_ehi + (size_t)(bcol + r) * ENC + c * 32 + ch * 4);
        cp16(st + BCOR_OFF + off, ecB + (size_t)(bcol + r) * 1024 + c * 128 + ch * 16);
    }
    asm volatile("cp.async.commit_group;" ::: "memory");
}

// Mainloop body, textually duplicated via macro (acc stays in registers)
#define GEMM_MAINLOOP(dsm, brow, bcol)                                          \
    load_stage(dsm,         brow, bcol, 0, tid);                                \
    load_stage(dsm + STAGE, brow, bcol, 1, tid);                                \
    _Pragma("unroll")                                                           \
    for (int c = 0; c < NCHUNK; ++c) {                                          \
        if (c == NCHUNK - 1) asm volatile("cp.async.wait_group 0;" ::: "memory");\
        else                 asm volatile("cp.async.wait_group 1;" ::: "memory");\
        __syncthreads();                                                        \
        const uint32_t st = dsm + (c & 1) * STAGE;                              \
        _Pragma("unroll")                                                       \
        for (int ks = 0; ks < 4; ++ks) {                                        \
            uint32_t ahi[2][4], aco[2][4], bhi[8][2], bco[8][2];                \
            _Pragma("unroll")                                                   \
            for (int im = 0; im < 2; ++im) {                                    \
                uint32_t off = SWZ((uint32_t)((a_row + im * 16) * 128 + ks * 32 + a_kb)); \
                ldsm4(ahi[im], st + AF32_OFF + off);                            \
                ldsm4(aco[im], st + ACOR_OFF + off);                            \
            }                                                                   \
            _Pragma("unroll")                                                   \
            for (int jn = 0; jn < 4; ++jn) {                                    \
                uint32_t off = SWZ((uint32_t)((b_row + jn * 16) * 128 + ks * 32 + b_kb)); \
                uint32_t rh[4], rc[4];                                          \
                ldsm4(rh, st + BF32_OFF + off);                                 \
                ldsm4(rc, st + BCOR_OFF + off);                                 \
                bhi[2 * jn][0] = rh[0]; bhi[2 * jn][1] = rh[1];                 \
                bhi[2 * jn + 1][0] = rh[2]; bhi[2 * jn + 1][1] = rh[3];         \
                bco[2 * jn][0] = rc[0]; bco[2 * jn][1] = rc[1];                 \
                bco[2 * jn + 1][0] = rc[2]; bco[2 * jn + 1][1] = rc[3];         \
            }                                                                   \
            _Pragma("unroll")                                                   \
            for (int im = 0; im < 2; ++im)                                      \
                _Pragma("unroll")                                               \
                for (int j = 0; j < 8; ++j) {                                   \
                    mma_tf32(acc[im][j], ahi[im], bhi[j]);                      \
                    mma_bf16(acc[im][j], aco[im], bco[j]);                      \
                }                                                               \
        }                                                                       \
        __syncthreads();                                                        \
        if (c + 2 < NCHUNK)                                                     \
            load_stage(dsm + (c & 1) * STAGE, brow, bcol, c + 2, tid);          \
    }

// ------------------------------------------------------------------
// Kernel 3a: bound GEMM — columns [0,256) only, writes g_sub.
// ------------------------------------------------------------------
__global__ __launch_bounds__(NTHREADS, 1)
void bound_gemm() {
    const int brow = blockIdx.y * BM;
    if (brow >= g_nuniq) return;

    extern __shared__ char dsm_raw[];
    __shared__ float e2s[BN];
    __shared__ float q2s[BM];

    const int tid    = threadIdx.x;
    const int lane   = tid & 31;
    const int wid    = tid >> 5;
    const int warp_m = wid & 3;
    const int warp_n = wid >> 2;
    const uint32_t dsm = smem_u32(dsm_raw);

    for (int i = tid; i < BN; i += NTHREADS) e2s[i] = g_e2[i];
    for (int i = tid; i < BM; i += NTHREADS) q2s[i] = g_q2[brow + i];

    float acc[2][8][4];
    #pragma unroll
    for (int im = 0; im < 2; im++)
        #pragma unroll
        for (int j = 0; j < 8; j++)
            #pragma unroll
            for (int v = 0; v < 4; v++) acc[im][j][v] = 0.f;

    const int a_row = warp_m * 32 + (lane & 15);
    const int a_kb  = (lane >> 4) << 4;
    const int b_row = warp_n * 64 + ((lane >> 4) << 3) + (lane & 7);
    const int b_kb  = ((lane >> 3) & 1) << 4;

    GEMM_MAINLOOP(dsm, brow, 0)

    #pragma unroll
    for (int im = 0; im < 2; ++im) {
        const int r0 = warp_m * 32 + im * 16 + (lane >> 2);
        const float q2a = q2s[r0];
        const float q2b = q2s[r0 + 8];
        #pragma unroll
        for (int j = 0; j < 8; ++j) {
            const int cl = warp_n * 64 + j * 8 + 2 * (lane & 3);
            const float e0 = e2s[cl], e1 = e2s[cl + 1];
            float2 oa, ob;
            oa.x = fmaxf(fmaf(-2.f, acc[im][j][0], q2a + e0), 0.f);
            oa.y = fmaxf(fmaf(-2.f, acc[im][j][1], q2a + e1), 0.f);
            ob.x = fmaxf(fmaf(-2.f, acc[im][j][2], q2b + e0), 0.f);
            ob.y = fmaxf(fmaf(-2.f, acc[im][j][3], q2b + e1), 0.f);
            *reinterpret_cast<float2*>(&g_sub[(size_t)(brow + r0) * 256 + cl]) = oa;
            *reinterpret_cast<float2*>(&g_sub[(size_t)(brow + r0 + 8) * 256 + cl]) = ob;
        }
    }
}

// ------------------------------------------------------------------
// Kernel 3b: per-row bound = exact 26th-smallest of subset + margin
// ------------------------------------------------------------------
__global__ __launch_bounds__(256)
void bound_select() {
    const int s = blockIdx.x;
    if (s >= g_nuniq) return;
    const int tid = threadIdx.x;
    __shared__ float sv[256];
    sv[tid] = g_sub[(size_t)s * 256 + tid];
    __syncthreads();
    float vi = sv[tid];
    int l = 0, e = 0;
    #pragma unroll 8
    for (int j = 0; j < 256; j++) {
        float vj = sv[j];
        l += (vj < vi);
        e += (vj == vi);
    }
    if (l <= K_RANK && K_RANK < l + e)
        g_bound[s] = vi + 0.25f;
}

// ------------------------------------------------------------------
// Kernel 3c: main GEMM — pushes candidates (val < bound), no d2 store.
// ------------------------------------------------------------------
__device__ __forceinline__ void push_cand(int row, float v, int col) {
    unsigned int p = atomicAdd(&g_ccount[row], 1u);
    if (p < CAP)
        g_cand[(size_t)row * CAP + p] = make_uint2(__float_as_uint(v), (unsigned)col);
}

__global__ __launch_bounds__(NTHREADS, 1)
void dist_gemm_mma() {
    const int brow = blockIdx.y * BM;
    if (brow >= g_nuniq) return;

    extern __shared__ char dsm_raw[];
    __shared__ float e2s[BN];
    __shared__ float q2s[BM];
    __shared__ float bnds[BM];

    const int tid    = threadIdx.x;
    const int lane   = tid & 31;
    const int wid    = tid >> 5;
    const int warp_m = wid & 3;
    const int warp_n = wid >> 2;
    const int bcol   = blockIdx.x * BN;
    const uint32_t dsm = smem_u32(dsm_raw);

    for (int i = tid; i < BN; i += NTHREADS) e2s[i] = g_e2[bcol + i];
    for (int i = tid; i < BM; i += NTHREADS) {
        q2s[i]  = g_q2[brow + i];
        bnds[i] = g_bound[brow + i];
    }

    float acc[2][8][4];
    #pragma unroll
    for (int im = 0; im < 2; im++)
        #pragma unroll
        for (int j = 0; j < 8; j++)
            #pragma unroll
            for (int v = 0; v < 4; v++) acc[im][j][v] = 0.f;

    const int a_row = warp_m * 32 + (lane & 15);
    const int a_kb  = (lane >> 4) << 4;
    const int b_row = warp_n * 64 + ((lane >> 4) << 3) + (lane & 7);
    const int b_kb  = ((lane >> 3) & 1) << 4;

    GEMM_MAINLOOP(dsm, brow, bcol)

    #pragma unroll
    for (int im = 0; im < 2; ++im) {
        const int rl = warp_m * 32 + im * 16 + (lane >> 2);
        const int ra = brow + rl;
        const float q2a = q2s[rl];
        const float q2b = q2s[rl + 8];
        const float ba = bnds[rl];
        const float bb = bnds[rl + 8];
        #pragma unroll
        for (int j = 0; j < 8; ++j) {
            const int cl = warp_n * 64 + j * 8 + 2 * (lane & 3);
            const int col = bcol + cl;
            const float e0 = e2s[cl], e1 = e2s[cl + 1];
            float v0 = fmaxf(fmaf(-2.f, acc[im][j][0], q2a + e0), 0.f);
            float v1 = fmaxf(fmaf(-2.f, acc[im][j][1], q2a + e1), 0.f);
            float v2 = fmaxf(fmaf(-2.f, acc[im][j][2], q2b + e0), 0.f);
            float v3 = fmaxf(fmaf(-2.f, acc[im][j][3], q2b + e1), 0.f);
            if (v0 < ba) push_cand(ra, v0, col);
            if (v1 < ba) push_cand(ra, v1, col + 1);
            if (v2 < bb) push_cand(ra + 8, v2, col);
            if (v3 < bb) push_cand(ra + 8, v3, col + 1);
        }
    }
}

// ------------------------------------------------------------------
// Kernel 4: select over candidate lists. Exact.
// Rank-25 via 32-step block binary search on value bits (O(m) per
// probe, broadcast SMEM reads) — replaces the O(m^2) scan that
// caused the R13/R14 collapse.
// ------------------------------------------------------------------
__global__ __launch_bounds__(256)
void select_kernel() {
    const int s = blockIdx.x;
    if (s >= g_nuniq) return;
    const int tid  = threadIdx.x;
    const int lane = tid & 31;
    const int wid  = tid >> 5;

    __shared__ uint32_t cand_v[CAP];     // 16 KB
    __shared__ uint32_t cand_c[CAP];     // 16 KB
    __shared__ uint32_t wred[8];
    __shared__ int counts[C_DIM];

    const unsigned int mcnt = g_ccount[s];
    if (tid < C_DIM) counts[tid] = 0;

    if (mcnt <= CAP) {
        const int m = (int)mcnt;
        for (int i = tid; i < m; i += 256) {
            uint2 c = g_cand[(size_t)s * CAP + i];
            cand_v[i] = c.x;
            cand_c[i] = c.y;
        }
        __syncthreads();

        // block count of candidates strictly below X
        auto count_lt = [&](uint32_t X) -> int {
            int c = 0;
            for (int i = tid; i < m; i += 256) c += (int)(cand_v[i] < X);
            #pragma unroll
            for (int o = 16; o > 0; o >>= 1)
                c += __shfl_xor_sync(0xFFFFFFFFu, c, o);
            if (lane == 0) wred[wid] = (uint32_t)c;
            __syncthreads();
            int t = 0;
            #pragma unroll
            for (int w = 0; w < 8; w++) t += (int)wred[w];
            __syncthreads();
            return t;
        };

        // smallest hi with count_lt(hi) >= 26  =>  kth bits = hi - 1
        uint32_t lo = 0, hi = 0x7F800001u;
        while (hi - lo > 1) {
            uint32_t mid = lo + ((hi - lo) >> 1);
            if (count_lt(mid) >= K_RANK + 1) hi = mid;
            else                             lo = mid;
        }
        const uint32_t kbits = hi - 1;

        for (int i = tid; i < m; i += 256) {
            if (cand_v[i] < kbits)
                atomicAdd(&counts[g_grp[cand_c[i]]], 1);
        }
        __syncthreads();
    } else {
        // ---- overflow fallback (essentially never): fp32 recompute +
        //      binary search on value bits. Exact.
        __shared__ float qsh[ENC];
        for (int d = tid; d < ENC; d += 256)
            qsh[d] = g_qhi[(size_t)s * ENC + d] +
                     __bfloat162float(g_qcA[(size_t)s * 2 * ENC + ENC + d]);
        __syncthreads();
        const float q2v = g_q2[s];

        uint32_t v[32];
        for (int k = 0; k < 32; k++) {
            int col = tid + k * 256;
            float a = 0.f;
            for (int d = 0; d < ENC; d++) {
                float ev = g_ehi[(size_t)col * ENC + d] +
                           __bfloat162float(g_ecB[(size_t)col * 2 * ENC + d]);
                a = fmaf(qsh[d], ev, a);
            }
            v[k] = __float_as_uint(fmaxf(q2v + g_e2[col] - 2.f * a, 0.f));
        }

        auto count_lt = [&](uint32_t X) -> int {
            int c = 0;
            for (int k = 0; k < 32; k++) c += (int)(v[k] < X);
            #pragma unroll
            for (int o = 16; o > 0; o >>= 1)
                c += __shfl_xor_sync(0xFFFFFFFFu, c, o);
            if (lane == 0) wred[wid] = (uint32_t)c;
            __syncthreads();
            int t = 0;
            #pragma unroll
            for (int w = 0; w < 8; w++) t += (int)wred[w];
            __syncthreads();
            return t;
        };

        uint32_t lo = 0, hi = 0x7F800001u;
        while (hi - lo > 1) {
            uint32_t mid = lo + ((hi - lo) >> 1);
            if (count_lt(mid) >= K_RANK + 1) hi = mid;
            else                             lo = mid;
        }
        const uint32_t kbits = hi - 1;

        for (int k = 0; k < 32; k++) {
            if (v[k] < kbits)
                atomicAdd(&counts[g_grp[tid + k * 256]], 1);
        }
        __syncthreads();
    }

    if (tid == 0) {
        int n = 0;
        #pragma unroll
        for (int c = 0; c < C_DIM; c++) n += counts[c];
        float inv = 1.0f / (float)n;
        float purity = 0.f;
        #pragma unroll
        for (int c = 0; c < C_DIM; c++) {
            float p = (float)counts[c] * inv;
            purity -= p * logf(p + 1e-5f);
        }
        g_res[s] = purity * g_maxg[g_uidxs[s]];
    }
}

// ------------------------------------------------------------------
// Kernel 5: scatter per-slot results to all duplicate samples
// ------------------------------------------------------------------
__global__ void scatter_kernel(const int* __restrict__ idxs,
                               float* __restrict__ out) {
    int s = blockIdx.x * blockDim.x + threadIdx.x;
    if (s < S_DIM) out[s] = g_res[g_uslot[idxs[s]]];
}

// ------------------------------------------------------------------
// Launch
// ------------------------------------------------------------------
extern "C" void kernel_launch(void* const* d_in, const int* in_sizes, int n_in,
                              void* d_out, int out_size) {
    const float* enc  = (const float*)d_in[0];
    const float* cat  = (const float*)d_in[1];
    const int*   idxs = (const int*)d_in[2];
    float* out = (float*)d_out;

    static bool attr_done = false;
    if (!attr_done) {
        cudaFuncSetAttribute(dist_gemm_mma,
                             cudaFuncAttributeMaxDynamicSharedMemorySize, GEMM_SMEM);
        cudaFuncSetAttribute(bound_gemm,
                             cudaFuncAttributeMaxDynamicSharedMemorySize, GEMM_SMEM);
        attr_done = true;
    }

    init_kernel<<<32, 256>>>();
    prep_kernel<<<B_DIM, 256>>>(enc, cat);
    mark_kernel<<<S_DIM / 256, 256>>>(idxs);
    gather_kernel<<<S_DIM, 64>>>();

    dim3 bgrid(1, S_DIM / BM);
    bound_gemm<<<bgrid, NTHREADS, GEMM_SMEM>>>();
    bound_select<<<S_DIM, 256>>>();

    dim3 grid(B_DIM / BN, S_DIM / BM);
    dist_gemm_mma<<<grid, NTHREADS, GEMM_SMEM>>>();

    select_kernel<<<S_DIM, 256>>>();
    scatter_kernel<<<S_DIM / 256, 256>>>(idxs, out);
}

// round 16
// speedup vs baseline: 4.2135x; 1.8603x over previous
#include <cuda_runtime.h>
#include <cuda_bf16.h>
#include <cstdint>

// Problem constants
#define S_DIM 8192
#define B_DIM 8192
#define ENC 256
#define C_DIM 25
#define K_RANK 25   // 0-based rank -> 26th smallest

// ------------------------------------------------------------------
// Scratch (device globals; allocation-free per harness rules)
// ------------------------------------------------------------------
__device__ __align__(256) float g_d2[(size_t)S_DIM * B_DIM];            // 268 MB
__device__ __align__(256) float g_ehi[(size_t)B_DIM * ENC];             // tf32(e)
__device__ __align__(256) float g_qhi[(size_t)S_DIM * ENC];             // gathered tf32(q), unique
__device__ __align__(256) __nv_bfloat16 g_ecA[(size_t)B_DIM * 2 * ENC]; // [qh16 | ql16]
__device__ __align__(256) __nv_bfloat16 g_ecB[(size_t)B_DIM * 2 * ENC]; // [el16 | eh16]
__device__ __align__(256) __nv_bfloat16 g_qcA[(size_t)S_DIM * 2 * ENC]; // gathered corr-A, unique
__device__ __align__(256) unsigned int g_cbmin[(size_t)S_DIM * 32];     // per-row col-block mins
__device__ float g_e2[B_DIM];
__device__ float g_q2[S_DIM];
__device__ float g_maxg[B_DIM];
__device__ unsigned char g_grp[B_DIM];
// dedup machinery
__device__ int g_present[B_DIM];
__device__ int g_uslot[B_DIM];
__device__ int g_uidxs[S_DIM];
__device__ int g_nuniq;
__device__ float g_res[S_DIM];

// ------------------------------------------------------------------
// Base-ISA PTX helpers (harness compiles via compute_103: NO 'a' features)
// ------------------------------------------------------------------
__device__ __forceinline__ uint32_t smem_u32(const void* p) {
    uint32_t a;
    asm("{ .reg .u64 t; cvta.to.shared.u64 t, %1; cvt.u32.u64 %0, t; }"
        : "=r"(a) : "l"(p));
    return a;
}
__device__ __forceinline__ float tf32_rn(float x) {
    uint32_t u;
    asm("cvt.rna.tf32.f32 %0, %1;" : "=r"(u) : "f"(x));
    return __uint_as_float(u);
}
__device__ __forceinline__ void cp16(uint32_t dst, const void* src) {
    asm volatile("cp.async.cg.shared.global [%0], [%1], 16;" :: "r"(dst), "l"(src));
}
__device__ __forceinline__ void ldsm4(uint32_t* r, uint32_t addr) {
    asm volatile("ldmatrix.sync.aligned.m8n8.x4.shared.b16 {%0,%1,%2,%3}, [%4];"
                 : "=r"(r[0]), "=r"(r[1]), "=r"(r[2]), "=r"(r[3]) : "r"(addr));
}
__device__ __forceinline__ void mma_tf32(float* c, const uint32_t* a, const uint32_t* b) {
    asm volatile(
        "mma.sync.aligned.m16n8k8.row.col.f32.tf32.tf32.f32 "
        "{%0,%1,%2,%3}, {%4,%5,%6,%7}, {%8,%9}, {%0,%1,%2,%3};"
        : "+f"(c[0]), "+f"(c[1]), "+f"(c[2]), "+f"(c[3])
        : "r"(a[0]), "r"(a[1]), "r"(a[2]), "r"(a[3]), "r"(b[0]), "r"(b[1]));
}
__device__ __forceinline__ void mma_bf16(float* c, const uint32_t* a, const uint32_t* b) {
    asm volatile(
        "mma.sync.aligned.m16n8k16.row.col.f32.bf16.bf16.f32 "
        "{%0,%1,%2,%3}, {%4,%5,%6,%7}, {%8,%9}, {%0,%1,%2,%3};"
        : "+f"(c[0]), "+f"(c[1]), "+f"(c[2]), "+f"(c[3])
        : "r"(a[0]), "r"(a[1]), "r"(a[2]), "r"(a[3]), "r"(b[0]), "r"(b[1]));
}
#define SWZ(o) ((o) ^ (((o) >> 3) & 0x70))

// ------------------------------------------------------------------
// Kernel 0: init cbmin table + dedup state
// ------------------------------------------------------------------
__global__ void init_kernel() {
    int i = blockIdx.x * blockDim.x + threadIdx.x;   // 65536 threads
    uint4 ff = make_uint4(0xFFFFFFFFu, 0xFFFFFFFFu, 0xFFFFFFFFu, 0xFFFFFFFFu);
    reinterpret_cast<uint4*>(g_cbmin)[i] = ff;
    if (i < B_DIM) g_present[i] = 0;
    if (i == 0) g_nuniq = 0;
}

// ------------------------------------------------------------------
// Kernel 1: e2, argmax/max, tf32 + bf16 splits.  One block per b-row.
// ------------------------------------------------------------------
__global__ void prep_kernel(const float* __restrict__ enc,
                            const float* __restrict__ cat) {
    int b = blockIdx.x;
    int t = threadIdx.x;

    float v  = enc[(size_t)b * ENC + t];
    float hi = tf32_rn(v);
    float lo = v - hi;
    g_ehi[(size_t)b * ENC + t] = hi;
    __nv_bfloat16 h16 = __float2bfloat16(hi);
    __nv_bfloat16 l16 = __float2bfloat16(lo);
    g_ecA[(size_t)b * 2 * ENC + t]       = h16;
    g_ecA[(size_t)b * 2 * ENC + ENC + t] = l16;
    g_ecB[(size_t)b * 2 * ENC + t]       = l16;
    g_ecB[(size_t)b * 2 * ENC + ENC + t] = h16;

    float sq = v * v;
    #pragma unroll
    for (int o = 16; o > 0; o >>= 1) sq += __shfl_xor_sync(0xFFFFFFFFu, sq, o);

    __shared__ float ws[8];
    if ((t & 31) == 0) ws[t >> 5] = sq;
    __syncthreads();
    if (t == 0) {
        float s = 0.f;
        #pragma unroll
        for (int i = 0; i < 8; i++) s += ws[i];
        g_e2[b] = s;
    }

    if (t < 32) {
        float mv = -1e30f;
        int   mi = 0x7FFFFFFF;
        if (t < C_DIM) { mv = cat[(size_t)b * C_DIM + t]; mi = t; }
        #pragma unroll
        for (int o = 16; o > 0; o >>= 1) {
            float ov = __shfl_xor_sync(0xFFFFFFFFu, mv, o);
            int   oi = __shfl_xor_sync(0xFFFFFFFFu, mi, o);
            if (ov > mv || (ov == mv && oi < mi)) { mv = ov; mi = oi; }
        }
        if (t == 0) { g_maxg[b] = mv; g_grp[b] = (unsigned char)mi; }
    }
}

// ------------------------------------------------------------------
// Kernel 1b: mark unique idx values, assign slots
// ------------------------------------------------------------------
__global__ void mark_kernel(const int* __restrict__ idxs) {
    int s = blockIdx.x * blockDim.x + threadIdx.x;
    if (s < S_DIM) {
        int idx = idxs[s];
        if (atomicCAS(&g_present[idx], 0, 1) == 0) {
            int slot = atomicAdd(&g_nuniq, 1);
            g_uslot[idx]  = slot;
            g_uidxs[slot] = idx;
        }
    }
}

// ------------------------------------------------------------------
// Kernel 2: gather unique q rows (tf32 + corrA) + q2
// ------------------------------------------------------------------
__global__ void gather_kernel() {
    int slot = blockIdx.x, t = threadIdx.x;   // 64 threads
    if (slot >= g_nuniq) return;
    int idx = g_uidxs[slot];
    const float4* sh = reinterpret_cast<const float4*>(&g_ehi[(size_t)idx * ENC]);
    float4* dh = reinterpret_cast<float4*>(&g_qhi[(size_t)slot * ENC]);
    dh[t] = sh[t];
    const uint4* sc = reinterpret_cast<const uint4*>(&g_ecA[(size_t)idx * 2 * ENC]);
    uint4* dc = reinterpret_cast<uint4*>(&g_qcA[(size_t)slot * 2 * ENC]);
    dc[t] = sc[t];
    if (t == 0) g_q2[slot] = g_e2[idx];
}

// ------------------------------------------------------------------
// Kernel 3: mixed tf32 + bf16 GEMM -> d2 over UNIQUE rows only.
// R9 config: 256 threads, warp grid 2(M) x 4(N), warp tile 64x64.
// ------------------------------------------------------------------
#define BM 128
#define BN 256
#define NCHUNK 8
#define AF32_OFF 0
#define ACOR_OFF (128 * 128)
#define BF32_OFF (2 * 128 * 128)
#define BCOR_OFF (BF32_OFF + 256 * 128)
#define STAGE    (BCOR_OFF + 256 * 128)         // 96 KB
#define GEMM_SMEM (2 * STAGE)                   // 192 KB

__device__ __forceinline__ void load_stage(uint32_t st, int brow, int bcol,
                                           int c, int tid) {
    const char* qcA = reinterpret_cast<const char*>(g_qcA);
    const char* ecB = reinterpret_cast<const char*>(g_ecB);
    #pragma unroll
    for (int it = 0; it < 4; ++it) {
        int i = tid + it * 256;
        int r = i >> 3, ch = i & 7;
        uint32_t off = SWZ((uint32_t)(r * 128 + ch * 16));
        cp16(st + AF32_OFF + off, g_qhi + (size_t)(brow + r) * ENC + c * 32 + ch * 4);
        cp16(st + ACOR_OFF + off, qcA + (size_t)(brow + r) * 1024 + c * 128 + ch * 16);
    }
    #pragma unroll
    for (int it = 0; it < 8; ++it) {
        int i = tid + it * 256;
        int r = i >> 3, ch = i & 7;
        uint32_t off = SWZ((uint32_t)(r * 128 + ch * 16));
        cp16(st + BF32_OFF + off, g_ehi + (size_t)(bcol + r) * ENC + c * 32 + ch * 4);
        cp16(st + BCOR_OFF + off, ecB + (size_t)(bcol + r) * 1024 + c * 128 + ch * 16);
    }
    asm volatile("cp.async.commit_group;" ::: "memory");
}

__global__ __launch_bounds__(256, 1)
void dist_gemm_mma() {
    const int brow = blockIdx.y * BM;
    if (brow >= g_nuniq) return;

    extern __shared__ char dsm_raw[];
    __shared__ float e2s[BN];
    __shared__ float q2s[BM];

    const int tid    = threadIdx.x;
    const int lane   = tid & 31;
    const int wid    = tid >> 5;
    const int warp_m = wid & 1;
    const int warp_n = wid >> 1;
    const int bcol   = blockIdx.x * BN;

    const uint32_t dsm = smem_u32(dsm_raw);

    for (int i = tid; i < BN; i += 256) e2s[i] = g_e2[bcol + i];
    for (int i = tid; i < BM; i += 256) q2s[i] = g_q2[brow + i];

    float acc[4][8][4];
    #pragma unroll
    for (int im = 0; im < 4; im++)
        #pragma unroll
        for (int j = 0; j < 8; j++)
            #pragma unroll
            for (int v = 0; v < 4; v++) acc[im][j][v] = 0.f;

    const int a_row = warp_m * 64 + (lane & 15);
    const int a_kb  = (lane >> 4) << 4;
    const int b_row = warp_n * 64 + ((lane >> 4) << 3) + (lane & 7);
    const int b_kb  = ((lane >> 3) & 1) << 4;

    load_stage(dsm,         brow, bcol, 0, tid);
    load_stage(dsm + STAGE, brow, bcol, 1, tid);

    #pragma unroll
    for (int c = 0; c < NCHUNK; ++c) {
        if (c == NCHUNK - 1) asm volatile("cp.async.wait_group 0;" ::: "memory");
        else                 asm volatile("cp.async.wait_group 1;" ::: "memory");
        __syncthreads();

        const uint32_t st = dsm + (c & 1) * STAGE;

        #pragma unroll
        for (int ks = 0; ks < 4; ++ks) {
            uint32_t ahi[4][4], aco[4][4], bhi[8][2], bco[8][2];
            #pragma unroll
            for (int im = 0; im < 4; ++im) {
                uint32_t off = SWZ((uint32_t)((a_row + im * 16) * 128 + ks * 32 + a_kb));
                ldsm4(ahi[im], st + AF32_OFF + off);
                ldsm4(aco[im], st + ACOR_OFF + off);
            }
            #pragma unroll
            for (int jn = 0; jn < 4; ++jn) {
                uint32_t off = SWZ((uint32_t)((b_row + jn * 16) * 128 + ks * 32 + b_kb));
                uint32_t rh[4], rc[4];
                ldsm4(rh, st + BF32_OFF + off);
                ldsm4(rc, st + BCOR_OFF + off);
                bhi[2 * jn][0] = rh[0]; bhi[2 * jn][1] = rh[1];
                bhi[2 * jn + 1][0] = rh[2]; bhi[2 * jn + 1][1] = rh[3];
                bco[2 * jn][0] = rc[0]; bco[2 * jn][1] = rc[1];
                bco[2 * jn + 1][0] = rc[2]; bco[2 * jn + 1][1] = rc[3];
            }
            #pragma unroll
            for (int im = 0; im < 4; ++im)
                #pragma unroll
                for (int j = 0; j < 8; ++j) {
                    mma_tf32(acc[im][j], ahi[im], bhi[j]);
                    mma_bf16(acc[im][j], aco[im], bco[j]);
                }
        }
        __syncthreads();
        if (c + 2 < NCHUNK)
            load_stage(dsm + (c & 1) * STAGE, brow, bcol, c + 2, tid);
    }

    // Epilogue: d2 = max(q2 + e2 - 2*acc, 0), plain stores, per-row block mins
    #pragma unroll
    for (int im = 0; im < 4; ++im) {
        const int r0 = warp_m * 64 + im * 16 + (lane >> 2);
        const float q2a = q2s[r0];
        const float q2b = q2s[r0 + 8];
        uint32_t mna = 0xFFFFFFFFu, mnb = 0xFFFFFFFFu;
        #pragma unroll
        for (int j = 0; j < 8; ++j) {
            const int cl = warp_n * 64 + j * 8 + 2 * (lane & 3);
            const float e0 = e2s[cl], e1 = e2s[cl + 1];
            float2 oa, ob;
            oa.x = fmaxf(fmaf(-2.f, acc[im][j][0], q2a + e0), 0.f);
            oa.y = fmaxf(fmaf(-2.f, acc[im][j][1], q2a + e1), 0.f);
            ob.x = fmaxf(fmaf(-2.f, acc[im][j][2], q2b + e0), 0.f);
            ob.y = fmaxf(fmaf(-2.f, acc[im][j][3], q2b + e1), 0.f);
            mna = min(mna, min(__float_as_uint(oa.x), __float_as_uint(oa.y)));
            mnb = min(mnb, min(__float_as_uint(ob.x), __float_as_uint(ob.y)));
            *reinterpret_cast<float2*>(&g_d2[(size_t)(brow + r0) * B_DIM + bcol + cl]) = oa;
            *reinterpret_cast<float2*>(&g_d2[(size_t)(brow + r0 + 8) * B_DIM + bcol + cl]) = ob;
        }
        mna = min(mna, __shfl_xor_sync(0xFFFFFFFFu, mna, 1));
        mna = min(mna, __shfl_xor_sync(0xFFFFFFFFu, mna, 2));
        mnb = min(mnb, __shfl_xor_sync(0xFFFFFFFFu, mnb, 1));
        mnb = min(mnb, __shfl_xor_sync(0xFFFFFFFFu, mnb, 2));
        if ((lane & 3) == 0) {
            atomicMin(&g_cbmin[(size_t)(brow + r0) * 32 + blockIdx.x], mna);
            atomicMin(&g_cbmin[(size_t)(brow + r0 + 8) * 32 + blockIdx.x], mnb);
        }
    }
}

// ------------------------------------------------------------------
// Kernel 4: bound-from-GEMM select over UNIQUE rows. Exact.
// R12 structure; rank step replaced by block binary search (O(m) probes).
// ------------------------------------------------------------------
#define CAND_CAP 2048

__global__ __launch_bounds__(256)
void select_kernel() {
    const int s = blockIdx.x;           // unique slot
    if (s >= g_nuniq) return;
    const int tid  = threadIdx.x;
    const int lane = tid & 31;
    const int wid  = tid >> 5;

    __shared__ uint32_t cand_v[CAND_CAP];     // 8 KB
    __shared__ uint32_t cand_i[CAND_CAP];     // 8 KB
    __shared__ uint32_t wred[8];
    __shared__ uint32_t sh_m;
    __shared__ uint32_t sh_B;
    __shared__ int counts[C_DIM];

    // Bound from GEMM by-product: max of 32 block mins
    if (wid == 0) {
        uint32_t b = g_cbmin[(size_t)s * 32 + lane];
        #pragma unroll
        for (int o = 16; o > 0; o >>= 1)
            b = max(b, __shfl_xor_sync(0xFFFFFFFFu, b, o));
        if (lane == 0) sh_B = b;
    }

    // Load row into registers (coalesced uint4)
    const uint4* row4 = reinterpret_cast<const uint4*>(g_d2 + (size_t)s * B_DIM);
    uint4 v[8];
    #pragma unroll
    for (int k = 0; k < 8; k++) v[k] = row4[tid + k * 256];

    if (tid == 0) sh_m = 0;
    __syncthreads();
    uint32_t B = sh_B;

    // count of row values strictly below X (fallback path only)
    auto row_count_lt = [&](uint32_t X) -> int {
        int c = 0;
        #pragma unroll
        for (int k = 0; k < 8; k++)
            c += (int)(v[k].x < X) + (int)(v[k].y < X) +
                 (int)(v[k].z < X) + (int)(v[k].w < X);
        #pragma unroll
        for (int o = 16; o > 0; o >>= 1)
            c += __shfl_xor_sync(0xFFFFFFFFu, c, o);
        if (lane == 0) wred[wid] = (uint32_t)c;
        __syncthreads();
        int t = 0;
        #pragma unroll
        for (int w = 0; w < 8; w++) t += (int)wred[w];
        __syncthreads();
        return t;
    };

    // Collect directly; expected m ~ 130 on first pass.
    int m = 0;
    bool direct = false;
    uint32_t direct_kbits = 0;
    for (int attempt = 0; attempt < 72; ++attempt) {
        #pragma unroll
        for (int k = 0; k < 8; k++) {
            uint32_t vv[4] = {v[k].x, v[k].y, v[k].z, v[k].w};
            #pragma unroll
            for (int j = 0; j < 4; j++) {
                if (vv[j] < B) {
                    uint32_t p = atomicAdd(&sh_m, 1u);
                    if (p < CAND_CAP) {
                        cand_v[p] = vv[j];
                        cand_i[p] = 4u * (uint32_t)(tid + k * 256) + (uint32_t)j;
                    }
                }
            }
        }
        __syncthreads();
        m = (int)sh_m;
        if (m >= 26 && m <= CAND_CAP) break;

        if (m < 26) {
            B += (1u << 20);
            if (B >= 0x7F800000u) B = 0x7F800001u;
        } else {
            uint32_t lo = 0;
            int cnt = m;
            while (cnt > CAND_CAP) {
                uint32_t mid = lo + ((B - lo) >> 1);
                if (mid == lo) { direct = true; direct_kbits = lo; break; }
                int c2 = row_count_lt(mid);
                if (c2 >= 26) { B = mid; cnt = c2; }
                else          { lo = mid; }
            }
            if (direct) break;
        }
        if (tid == 0) sh_m = 0;
        __syncthreads();
    }

    if (tid < C_DIM) counts[tid] = 0;
    __syncthreads();

    uint32_t kbits;
    if (!direct) {
        m = min(m, CAND_CAP);
        // block count of candidates strictly below X
        auto cand_count_lt = [&](uint32_t X) -> int {
            int c = 0;
            for (int i = tid; i < m; i += 256) c += (int)(cand_v[i] < X);
            #pragma unroll
            for (int o = 16; o > 0; o >>= 1)
                c += __shfl_xor_sync(0xFFFFFFFFu, c, o);
            if (lane == 0) wred[wid] = (uint32_t)c;
            __syncthreads();
            int t = 0;
            #pragma unroll
            for (int w = 0; w < 8; w++) t += (int)wred[w];
            __syncthreads();
            return t;
        };
        // smallest hi with count >= 26  =>  kth bits = hi - 1
        uint32_t lo = 0, hi = 0x7F800001u;
        while (hi - lo > 1) {
            uint32_t mid = lo + ((hi - lo) >> 1);
            if (cand_count_lt(mid) >= K_RANK + 1) hi = mid;
            else                                  lo = mid;
        }
        kbits = hi - 1;
    } else {
        kbits = direct_kbits;
    }

    // Bincount of neighbours (val < kbits)
    if (!direct) {
        for (int i = tid; i < m; i += 256) {
            if (cand_v[i] < kbits)
                atomicAdd(&counts[g_grp[cand_i[i]]], 1);
        }
    } else {
        #pragma unroll
        for (int k = 0; k < 8; k++) {
            uint32_t vv[4] = {v[k].x, v[k].y, v[k].z, v[k].w};
            #pragma unroll
            for (int j = 0; j < 4; j++) {
                if (vv[j] < kbits)
                    atomicAdd(&counts[g_grp[4 * (tid + k * 256) + j]], 1);
            }
        }
    }
    __syncthreads();

    if (tid == 0) {
        int n = 0;
        #pragma unroll
        for (int c = 0; c < C_DIM; c++) n += counts[c];
        float inv = 1.0f / (float)n;
        float purity = 0.f;
        #pragma unroll
        for (int c = 0; c < C_DIM; c++) {
            float p = (float)counts[c] * inv;
            purity -= p * logf(p + 1e-5f);
        }
        g_res[s] = purity * g_maxg[g_uidxs[s]];
    }
}

// ------------------------------------------------------------------
// Kernel 5: scatter per-slot results to all duplicate samples
// ------------------------------------------------------------------
__global__ void scatter_kernel(const int* __restrict__ idxs,
                               float* __restrict__ out) {
    int s = blockIdx.x * blockDim.x + threadIdx.x;
    if (s < S_DIM) out[s] = g_res[g_uslot[idxs[s]]];
}

// ------------------------------------------------------------------
// Launch
// ------------------------------------------------------------------
extern "C" void kernel_launch(void* const* d_in, const int* in_sizes, int n_in,
                              void* d_out, int out_size) {
    const float* enc  = (const float*)d_in[0];
    const float* cat  = (const float*)d_in[1];
    const int*   idxs = (const int*)d_in[2];
    float* out = (float*)d_out;

    static bool attr_done = false;
    if (!attr_done) {
        cudaFuncSetAttribute(dist_gemm_mma,
                             cudaFuncAttributeMaxDynamicSharedMemorySize, GEMM_SMEM);
        attr_done = true;
    }

    init_kernel<<<256, 256>>>();
    prep_kernel<<<B_DIM, 256>>>(enc, cat);
    mark_kernel<<<S_DIM / 256, 256>>>(idxs);
    gather_kernel<<<S_DIM, 64>>>();

    dim3 grid(B_DIM / BN, S_DIM / BM);
    dist_gemm_mma<<<grid, 256, GEMM_SMEM>>>();

    select_kernel<<<S_DIM, 256>>>();
    scatter_kernel<<<S_DIM / 256, 256>>>(idxs, out);
}

// round 17
// speedup vs baseline: 4.7385x; 1.1246x over previous
#include <cuda_runtime.h>
#include <cuda_bf16.h>
#include <cstdint>

// Problem constants
#define S_DIM 8192
#define B_DIM 8192
#define ENC 256
#define C_DIM 25
#define K_RANK 25   // 0-based rank -> 26th smallest

// ------------------------------------------------------------------
// Scratch (device globals; allocation-free per harness rules)
// ------------------------------------------------------------------
__device__ __align__(256) float g_d2[(size_t)S_DIM * B_DIM];            // 268 MB
__device__ __align__(256) float g_ehi[(size_t)B_DIM * ENC];             // tf32(e)
__device__ __align__(256) float g_qhi[(size_t)S_DIM * ENC];             // gathered tf32(q), unique
__device__ __align__(256) __nv_bfloat16 g_ecA[(size_t)B_DIM * 2 * ENC]; // [qh16 | ql16]
__device__ __align__(256) __nv_bfloat16 g_ecB[(size_t)B_DIM * 2 * ENC]; // [el16 | eh16]
__device__ __align__(256) __nv_bfloat16 g_qcA[(size_t)S_DIM * 2 * ENC]; // gathered corr-A, unique
__device__ __align__(256) unsigned int g_cbmin[(size_t)S_DIM * 32];     // per-row col-block mins
__device__ float g_e2[B_DIM];
__device__ float g_q2[S_DIM];
__device__ float g_maxg[B_DIM];
__device__ unsigned char g_grp[B_DIM];
// dedup machinery
__device__ int g_present[B_DIM];
__device__ int g_uslot[B_DIM];
__device__ int g_uidxs[S_DIM];
__device__ int g_nuniq;
__device__ float g_res[S_DIM];

// ------------------------------------------------------------------
// Base-ISA PTX helpers (harness compiles via compute_103: NO 'a' features)
// ------------------------------------------------------------------
__device__ __forceinline__ uint32_t smem_u32(const void* p) {
    uint32_t a;
    asm("{ .reg .u64 t; cvta.to.shared.u64 t, %1; cvt.u32.u64 %0, t; }"
        : "=r"(a) : "l"(p));
    return a;
}
__device__ __forceinline__ float tf32_rn(float x) {
    uint32_t u;
    asm("cvt.rna.tf32.f32 %0, %1;" : "=r"(u) : "f"(x));
    return __uint_as_float(u);
}
__device__ __forceinline__ void cp16(uint32_t dst, const void* src) {
    asm volatile("cp.async.cg.shared.global [%0], [%1], 16;" :: "r"(dst), "l"(src));
}
__device__ __forceinline__ void ldsm4(uint32_t* r, uint32_t addr) {
    asm volatile("ldmatrix.sync.aligned.m8n8.x4.shared.b16 {%0,%1,%2,%3}, [%4];"
                 : "=r"(r[0]), "=r"(r[1]), "=r"(r[2]), "=r"(r[3]) : "r"(addr));
}
__device__ __forceinline__ void mma_tf32(float* c, const uint32_t* a, const uint32_t* b) {
    asm volatile(
        "mma.sync.aligned.m16n8k8.row.col.f32.tf32.tf32.f32 "
        "{%0,%1,%2,%3}, {%4,%5,%6,%7}, {%8,%9}, {%0,%1,%2,%3};"
        : "+f"(c[0]), "+f"(c[1]), "+f"(c[2]), "+f"(c[3])
        : "r"(a[0]), "r"(a[1]), "r"(a[2]), "r"(a[3]), "r"(b[0]), "r"(b[1]));
}
__device__ __forceinline__ void mma_bf16(float* c, const uint32_t* a, const uint32_t* b) {
    asm volatile(
        "mma.sync.aligned.m16n8k16.row.col.f32.bf16.bf16.f32 "
        "{%0,%1,%2,%3}, {%4,%5,%6,%7}, {%8,%9}, {%0,%1,%2,%3};"
        : "+f"(c[0]), "+f"(c[1]), "+f"(c[2]), "+f"(c[3])
        : "r"(a[0]), "r"(a[1]), "r"(a[2]), "r"(a[3]), "r"(b[0]), "r"(b[1]));
}
#define SWZ(o) ((o) ^ (((o) >> 3) & 0x70))

// ------------------------------------------------------------------
// Kernel 0: init cbmin table + dedup state
// ------------------------------------------------------------------
__global__ void init_kernel() {
    int i = blockIdx.x * blockDim.x + threadIdx.x;   // 65536 threads
    uint4 ff = make_uint4(0xFFFFFFFFu, 0xFFFFFFFFu, 0xFFFFFFFFu, 0xFFFFFFFFu);
    reinterpret_cast<uint4*>(g_cbmin)[i] = ff;
    if (i < B_DIM) g_present[i] = 0;
    if (i == 0) g_nuniq = 0;
}

// ------------------------------------------------------------------
// Kernel 1: e2, argmax/max, tf32 + bf16 splits.  One block per b-row.
// ------------------------------------------------------------------
__global__ void prep_kernel(const float* __restrict__ enc,
                            const float* __restrict__ cat) {
    int b = blockIdx.x;
    int t = threadIdx.x;

    float v  = enc[(size_t)b * ENC + t];
    float hi = tf32_rn(v);
    float lo = v - hi;
    g_ehi[(size_t)b * ENC + t] = hi;
    __nv_bfloat16 h16 = __float2bfloat16(hi);
    __nv_bfloat16 l16 = __float2bfloat16(lo);
    g_ecA[(size_t)b * 2 * ENC + t]       = h16;
    g_ecA[(size_t)b * 2 * ENC + ENC + t] = l16;
    g_ecB[(size_t)b * 2 * ENC + t]       = l16;
    g_ecB[(size_t)b * 2 * ENC + ENC + t] = h16;

    float sq = v * v;
    #pragma unroll
    for (int o = 16; o > 0; o >>= 1) sq += __shfl_xor_sync(0xFFFFFFFFu, sq, o);

    __shared__ float ws[8];
    if ((t & 31) == 0) ws[t >> 5] = sq;
    __syncthreads();
    if (t == 0) {
        float s = 0.f;
        #pragma unroll
        for (int i = 0; i < 8; i++) s += ws[i];
        g_e2[b] = s;
    }

    if (t < 32) {
        float mv = -1e30f;
        int   mi = 0x7FFFFFFF;
        if (t < C_DIM) { mv = cat[(size_t)b * C_DIM + t]; mi = t; }
        #pragma unroll
        for (int o = 16; o > 0; o >>= 1) {
            float ov = __shfl_xor_sync(0xFFFFFFFFu, mv, o);
            int   oi = __shfl_xor_sync(0xFFFFFFFFu, mi, o);
            if (ov > mv || (ov == mv && oi < mi)) { mv = ov; mi = oi; }
        }
        if (t == 0) { g_maxg[b] = mv; g_grp[b] = (unsigned char)mi; }
    }
}

// ------------------------------------------------------------------
// Kernel 1b: mark unique idx values, assign slots
// ------------------------------------------------------------------
__global__ void mark_kernel(const int* __restrict__ idxs) {
    int s = blockIdx.x * blockDim.x + threadIdx.x;
    if (s < S_DIM) {
        int idx = idxs[s];
        if (atomicCAS(&g_present[idx], 0, 1) == 0) {
            int slot = atomicAdd(&g_nuniq, 1);
            g_uslot[idx]  = slot;
            g_uidxs[slot] = idx;
        }
    }
}

// ------------------------------------------------------------------
// Kernel 2: gather unique q rows (tf32 + corrA) + q2
// ------------------------------------------------------------------
__global__ void gather_kernel() {
    int slot = blockIdx.x, t = threadIdx.x;   // 64 threads
    if (slot >= g_nuniq) return;
    int idx = g_uidxs[slot];
    const float4* sh = reinterpret_cast<const float4*>(&g_ehi[(size_t)idx * ENC]);
    float4* dh = reinterpret_cast<float4*>(&g_qhi[(size_t)slot * ENC]);
    dh[t] = sh[t];
    const uint4* sc = reinterpret_cast<const uint4*>(&g_ecA[(size_t)idx * 2 * ENC]);
    uint4* dc = reinterpret_cast<uint4*>(&g_qcA[(size_t)slot * 2 * ENC]);
    dc[t] = sc[t];
    if (t == 0) g_q2[slot] = g_e2[idx];
}

// ------------------------------------------------------------------
// Kernel 3: mixed tf32 + bf16 GEMM -> d2 over UNIQUE rows only.
// R9/R12 config: 256 threads, warp grid 2(M) x 4(N), warp tile 64x64.
// ------------------------------------------------------------------
#define BM 128
#define BN 256
#define NCHUNK 8
#define AF32_OFF 0
#define ACOR_OFF (128 * 128)
#define BF32_OFF (2 * 128 * 128)
#define BCOR_OFF (BF32_OFF + 256 * 128)
#define STAGE    (BCOR_OFF + 256 * 128)         // 96 KB
#define GEMM_SMEM (2 * STAGE)                   // 192 KB

__device__ __forceinline__ void load_stage(uint32_t st, int brow, int bcol,
                                           int c, int tid) {
    const char* qcA = reinterpret_cast<const char*>(g_qcA);
    const char* ecB = reinterpret_cast<const char*>(g_ecB);
    #pragma unroll
    for (int it = 0; it < 4; ++it) {
        int i = tid + it * 256;
        int r = i >> 3, ch = i & 7;
        uint32_t off = SWZ((uint32_t)(r * 128 + ch * 16));
        cp16(st + AF32_OFF + off, g_qhi + (size_t)(brow + r) * ENC + c * 32 + ch * 4);
        cp16(st + ACOR_OFF + off, qcA + (size_t)(brow + r) * 1024 + c * 128 + ch * 16);
    }
    #pragma unroll
    for (int it = 0; it < 8; ++it) {
        int i = tid + it * 256;
        int r = i >> 3, ch = i & 7;
        uint32_t off = SWZ((uint32_t)(r * 128 + ch * 16));
        cp16(st + BF32_OFF + off, g_ehi + (size_t)(bcol + r) * ENC + c * 32 + ch * 4);
        cp16(st + BCOR_OFF + off, ecB + (size_t)(bcol + r) * 1024 + c * 128 + ch * 16);
    }
    asm volatile("cp.async.commit_group;" ::: "memory");
}

__global__ __launch_bounds__(256, 1)
void dist_gemm_mma() {
    const int brow = blockIdx.y * BM;
    if (brow >= g_nuniq) return;

    extern __shared__ char dsm_raw[];
    __shared__ float e2s[BN];
    __shared__ float q2s[BM];

    const int tid    = threadIdx.x;
    const int lane   = tid & 31;
    const int wid    = tid >> 5;
    const int warp_m = wid & 1;
    const int warp_n = wid >> 1;
    const int bcol   = blockIdx.x * BN;

    const uint32_t dsm = smem_u32(dsm_raw);

    for (int i = tid; i < BN; i += 256) e2s[i] = g_e2[bcol + i];
    for (int i = tid; i < BM; i += 256) q2s[i] = g_q2[brow + i];

    float acc[4][8][4];
    #pragma unroll
    for (int im = 0; im < 4; im++)
        #pragma unroll
        for (int j = 0; j < 8; j++)
            #pragma unroll
            for (int v = 0; v < 4; v++) acc[im][j][v] = 0.f;

    const int a_row = warp_m * 64 + (lane & 15);
    const int a_kb  = (lane >> 4) << 4;
    const int b_row = warp_n * 64 + ((lane >> 4) << 3) + (lane & 7);
    const int b_kb  = ((lane >> 3) & 1) << 4;

    load_stage(dsm,         brow, bcol, 0, tid);
    load_stage(dsm + STAGE, brow, bcol, 1, tid);

    #pragma unroll
    for (int c = 0; c < NCHUNK; ++c) {
        if (c == NCHUNK - 1) asm volatile("cp.async.wait_group 0;" ::: "memory");
        else                 asm volatile("cp.async.wait_group 1;" ::: "memory");
        __syncthreads();

        const uint32_t st = dsm + (c & 1) * STAGE;

        #pragma unroll
        for (int ks = 0; ks < 4; ++ks) {
            uint32_t ahi[4][4], aco[4][4], bhi[8][2], bco[8][2];
            #pragma unroll
            for (int im = 0; im < 4; ++im) {
                uint32_t off = SWZ((uint32_t)((a_row + im * 16) * 128 + ks * 32 + a_kb));
                ldsm4(ahi[im], st + AF32_OFF + off);
                ldsm4(aco[im], st + ACOR_OFF + off);
            }
            #pragma unroll
            for (int jn = 0; jn < 4; ++jn) {
                uint32_t off = SWZ((uint32_t)((b_row + jn * 16) * 128 + ks * 32 + b_kb));
                uint32_t rh[4], rc[4];
                ldsm4(rh, st + BF32_OFF + off);
                ldsm4(rc, st + BCOR_OFF + off);
                bhi[2 * jn][0] = rh[0]; bhi[2 * jn][1] = rh[1];
                bhi[2 * jn + 1][0] = rh[2]; bhi[2 * jn + 1][1] = rh[3];
                bco[2 * jn][0] = rc[0]; bco[2 * jn][1] = rc[1];
                bco[2 * jn + 1][0] = rc[2]; bco[2 * jn + 1][1] = rc[3];
            }
            #pragma unroll
            for (int im = 0; im < 4; ++im)
                #pragma unroll
                for (int j = 0; j < 8; ++j) {
                    mma_tf32(acc[im][j], ahi[im], bhi[j]);
                    mma_bf16(acc[im][j], aco[im], bco[j]);
                }
        }
        __syncthreads();
        if (c + 2 < NCHUNK)
            load_stage(dsm + (c & 1) * STAGE, brow, bcol, c + 2, tid);
    }

    // Epilogue: d2 = max(q2 + e2 - 2*acc, 0), plain stores, per-row block mins
    #pragma unroll
    for (int im = 0; im < 4; ++im) {
        const int r0 = warp_m * 64 + im * 16 + (lane >> 2);
        const float q2a = q2s[r0];
        const float q2b = q2s[r0 + 8];
        uint32_t mna = 0xFFFFFFFFu, mnb = 0xFFFFFFFFu;
        #pragma unroll
        for (int j = 0; j < 8; ++j) {
            const int cl = warp_n * 64 + j * 8 + 2 * (lane & 3);
            const float e0 = e2s[cl], e1 = e2s[cl + 1];
            float2 oa, ob;
            oa.x = fmaxf(fmaf(-2.f, acc[im][j][0], q2a + e0), 0.f);
            oa.y = fmaxf(fmaf(-2.f, acc[im][j][1], q2a + e1), 0.f);
            ob.x = fmaxf(fmaf(-2.f, acc[im][j][2], q2b + e0), 0.f);
            ob.y = fmaxf(fmaf(-2.f, acc[im][j][3], q2b + e1), 0.f);
            mna = min(mna, min(__float_as_uint(oa.x), __float_as_uint(oa.y)));
            mnb = min(mnb, min(__float_as_uint(ob.x), __float_as_uint(ob.y)));
            *reinterpret_cast<float2*>(&g_d2[(size_t)(brow + r0) * B_DIM + bcol + cl]) = oa;
            *reinterpret_cast<float2*>(&g_d2[(size_t)(brow + r0 + 8) * B_DIM + bcol + cl]) = ob;
        }
        mna = min(mna, __shfl_xor_sync(0xFFFFFFFFu, mna, 1));
        mna = min(mna, __shfl_xor_sync(0xFFFFFFFFu, mna, 2));
        mnb = min(mnb, __shfl_xor_sync(0xFFFFFFFFu, mnb, 1));
        mnb = min(mnb, __shfl_xor_sync(0xFFFFFFFFu, mnb, 2));
        if ((lane & 3) == 0) {
            atomicMin(&g_cbmin[(size_t)(brow + r0) * 32 + blockIdx.x], mna);
            atomicMin(&g_cbmin[(size_t)(brow + r0 + 8) * 32 + blockIdx.x], mnb);
        }
    }
}

// ------------------------------------------------------------------
// Kernel 4: bound-from-GEMM select over UNIQUE rows. Exact.
// R12 logic; 512 threads (VPT=4) for higher occupancy on the row stream.
// ------------------------------------------------------------------
#define CAND_CAP 2048
#define SEL_T 512

__global__ __launch_bounds__(SEL_T)
void select_kernel() {
    const int s = blockIdx.x;           // unique slot
    if (s >= g_nuniq) return;
    const int tid  = threadIdx.x;
    const int lane = tid & 31;
    const int wid  = tid >> 5;          // 0..15

    __shared__ uint32_t cand_v[CAND_CAP];     // 8 KB
    __shared__ uint32_t cand_i[CAND_CAP];     // 8 KB
    __shared__ uint32_t wred[16];
    __shared__ uint32_t sh_m;
    __shared__ uint32_t sh_B;
    __shared__ uint32_t sh_kbits;
    __shared__ int counts[C_DIM];

    // Bound from GEMM by-product: max of 32 block mins
    if (wid == 0) {
        uint32_t b = g_cbmin[(size_t)s * 32 + lane];
        #pragma unroll
        for (int o = 16; o > 0; o >>= 1)
            b = max(b, __shfl_xor_sync(0xFFFFFFFFu, b, o));
        if (lane == 0) sh_B = b;
    }

    // Load row into registers (coalesced uint4): 4 x 512 x 4 = 8192 values
    const uint4* row4 = reinterpret_cast<const uint4*>(g_d2 + (size_t)s * B_DIM);
    uint4 v[4];
    #pragma unroll
    for (int k = 0; k < 4; k++) v[k] = row4[tid + k * SEL_T];

    if (tid == 0) sh_m = 0;
    __syncthreads();
    uint32_t B = sh_B;

    // count of row values strictly below X (fallback path only)
    auto row_count_lt = [&](uint32_t X) -> int {
        int c = 0;
        #pragma unroll
        for (int k = 0; k < 4; k++)
            c += (int)(v[k].x < X) + (int)(v[k].y < X) +
                 (int)(v[k].z < X) + (int)(v[k].w < X);
        #pragma unroll
        for (int o = 16; o > 0; o >>= 1)
            c += __shfl_xor_sync(0xFFFFFFFFu, c, o);
        if (lane == 0) wred[wid] = (uint32_t)c;
        __syncthreads();
        int t = 0;
        #pragma unroll
        for (int w = 0; w < 16; w++) t += (int)wred[w];
        __syncthreads();
        return t;
    };

    // Collect directly; expected m ~ 130 on first pass.
    int m = 0;
    bool direct = false;
    uint32_t direct_kbits = 0;
    for (int attempt = 0; attempt < 72; ++attempt) {
        #pragma unroll
        for (int k = 0; k < 4; k++) {
            uint32_t vv[4] = {v[k].x, v[k].y, v[k].z, v[k].w};
            #pragma unroll
            for (int j = 0; j < 4; j++) {
                if (vv[j] < B) {
                    uint32_t p = atomicAdd(&sh_m, 1u);
                    if (p < CAND_CAP) {
                        cand_v[p] = vv[j];
                        cand_i[p] = 4u * (uint32_t)(tid + k * SEL_T) + (uint32_t)j;
                    }
                }
            }
        }
        __syncthreads();
        m = (int)sh_m;
        if (m >= 26 && m <= CAND_CAP) break;

        if (m < 26) {
            B += (1u << 20);
            if (B >= 0x7F800000u) B = 0x7F800001u;
        } else {
            uint32_t lo = 0;
            int cnt = m;
            while (cnt > CAND_CAP) {
                uint32_t mid = lo + ((B - lo) >> 1);
                if (mid == lo) { direct = true; direct_kbits = lo; break; }
                int c2 = row_count_lt(mid);
                if (c2 >= 26) { B = mid; cnt = c2; }
                else          { lo = mid; }
            }
            if (direct) break;
        }
        if (tid == 0) sh_m = 0;
        __syncthreads();
    }

    if (tid < C_DIM) counts[tid] = 0;
    __syncthreads();

    // Exact rank-25 among the m candidates (flat scan; m ~ 130 << SEL_T)
    if (!direct) {
        m = min(m, CAND_CAP);
        for (int i = tid; i < m; i += SEL_T) {
            uint32_t vi = cand_v[i];
            int l = 0, e = 0;
            for (int j = 0; j < m; j++) {
                uint32_t vj = cand_v[j];
                l += (vj < vi);
                e += (vj == vi);
            }
            if (l <= K_RANK && K_RANK < l + e) sh_kbits = vi;
        }
    } else if (tid == 0) {
        sh_kbits = direct_kbits;
    }
    __syncthreads();
    const uint32_t kbits = sh_kbits;

    // Bincount of neighbours (val < kbits)
    if (!direct) {
        for (int i = tid; i < m; i += SEL_T) {
            if (cand_v[i] < kbits)
                atomicAdd(&counts[g_grp[cand_i[i]]], 1);
        }
    } else {
        #pragma unroll
        for (int k = 0; k < 4; k++) {
            uint32_t vv[4] = {v[k].x, v[k].y, v[k].z, v[k].w};
            #pragma unroll
            for (int j = 0; j < 4; j++) {
                if (vv[j] < kbits)
                    atomicAdd(&counts[g_grp[4 * (tid + k * SEL_T) + j]], 1);
            }
        }
    }
    __syncthreads();

    if (tid == 0) {
        int n = 0;
        #pragma unroll
        for (int c = 0; c < C_DIM; c++) n += counts[c];
        float inv = 1.0f / (float)n;
        float purity = 0.f;
        #pragma unroll
        for (int c = 0; c < C_DIM; c++) {
            float p = (float)counts[c] * inv;
            purity -= p * logf(p + 1e-5f);
        }
        g_res[s] = purity * g_maxg[g_uidxs[s]];
    }
}

// ------------------------------------------------------------------
// Kernel 5: scatter per-slot results to all duplicate samples
// ------------------------------------------------------------------
__global__ void scatter_kernel(const int* __restrict__ idxs,
                               float* __restrict__ out) {
    int s = blockIdx.x * blockDim.x + threadIdx.x;
    if (s < S_DIM) out[s] = g_res[g_uslot[idxs[s]]];
}

// ------------------------------------------------------------------
// Launch
// ------------------------------------------------------------------
extern "C" void kernel_launch(void* const* d_in, const int* in_sizes, int n_in,
                              void* d_out, int out_size) {
    const float* enc  = (const float*)d_in[0];
    const float* cat  = (const float*)d_in[1];
    const int*   idxs = (const int*)d_in[2];
    float* out = (float*)d_out;

    static bool attr_done = false;
    if (!attr_done) {
        cudaFuncSetAttribute(dist_gemm_mma,
                             cudaFuncAttributeMaxDynamicSharedMemorySize, GEMM_SMEM);
        attr_done = true;
    }

    init_kernel<<<256, 256>>>();
    prep_kernel<<<B_DIM, 256>>>(enc, cat);
    mark_kernel<<<S_DIM / 256, 256>>>(idxs);
    gather_kernel<<<S_DIM, 64>>>();

    dim3 grid(B_DIM / BN, S_DIM / BM);
    dist_gemm_mma<<<grid, 256, GEMM_SMEM>>>();

    select_kernel<<<S_DIM, SEL_T>>>();
    scatter_kernel<<<S_DIM / 256, 256>>>(idxs, out);
}